// round 2
// baseline (speedup 1.0000x reference)
#include <cuda_runtime.h>
#include <math.h>

#define NN 50000
#define NE 800000
#define HD 64
#define NG 128
#define NL 3
#define MIN_D 133     // 2H + 1 + edge_dim(4)
#define MIN_PAD 136   // padded to multiple of 4, zero-filled

// ---------------- scratch (device globals; no allocation allowed) ----------------
__device__ float g_h[NN * HD];
__device__ float g_pos[NN * 3];
__device__ float g_agg[NN * HD];
__device__ float g_pacc[NN * 3];
__device__ float g_deg[NN];
__device__ float g_gsum[NG * HD];
__device__ float g_gcnt[NG];

__device__ __forceinline__ float silu_f(float x) {
    return x / (1.0f + __expf(-x));
}

// ---------------- init: h = emb[node_types], pos copy, deg = 0 ----------------
__global__ void init_kernel(const int* __restrict__ nt, const float* __restrict__ emb,
                            const float* __restrict__ pos) {
    int i = blockIdx.x * blockDim.x + threadIdx.x;
    int st = gridDim.x * blockDim.x;
    for (int j = i; j < NN * HD; j += st) g_h[j] = emb[nt[j >> 6] * HD + (j & 63)];
    for (int j = i; j < NN * 3; j += st) g_pos[j] = pos[j];
    for (int j = i; j < NN; j += st) g_deg[j] = 0.0f;
}

__global__ void deg_kernel(const int* __restrict__ ei) {
    int i = blockIdx.x * blockDim.x + threadIdx.x;
    int st = gridDim.x * blockDim.x;
    for (int e = i; e < NE; e += st) atomicAdd(&g_deg[ei[NE + e]], 1.0f);
}

__global__ void zero_layer_kernel() {
    int i = blockIdx.x * blockDim.x + threadIdx.x;
    int st = gridDim.x * blockDim.x;
    for (int j = i; j < NN * HD; j += st) g_agg[j] = 0.0f;
    for (int j = i; j < NN * 3; j += st) g_pacc[j] = 0.0f;
}

// ---------------- fused edge kernel: edge MLP + coord MLP + scatter ----------------
// Shared layout (floats):
//   sW1[MIN_PAD*64]  sW2[64*64]  sC1[64*64]  sC2[64]  sB1[64] sB2[64] sCB1[64]
//   per-warp buf: s_in[136] + s_m1[64]  (m2 reuses s_in[0..63])
#define EDGE_SMEM_F (MIN_PAD * HD + HD * HD + HD * HD + 4 * HD + 8 * (MIN_PAD + HD))
#define EDGE_SMEM_B (EDGE_SMEM_F * 4)

__global__ void edge_kernel(const int* __restrict__ ei, const float* __restrict__ ea,
                            const float* __restrict__ ew1, const float* __restrict__ eb1,
                            const float* __restrict__ ew2, const float* __restrict__ eb2,
                            const float* __restrict__ cw1, const float* __restrict__ cb1,
                            const float* __restrict__ cw2, const float* __restrict__ cb2,
                            int layer) {
    extern __shared__ float sm[];
    float* sW1 = sm;                         // 8704
    float* sW2 = sW1 + MIN_PAD * HD;         // 4096
    float* sC1 = sW2 + HD * HD;              // 4096
    float* sC2 = sC1 + HD * HD;              // 64
    float* sB1 = sC2 + HD;
    float* sB2 = sB1 + HD;
    float* sCB1 = sB2 + HD;
    float* sbuf = sCB1 + HD;

    int tid = threadIdx.x;
    const float* w1 = ew1 + layer * MIN_D * HD;
    for (int i = tid; i < MIN_PAD * HD; i += blockDim.x)
        sW1[i] = (i < MIN_D * HD) ? w1[i] : 0.0f;
    const float* w2 = ew2 + layer * HD * HD;
    const float* c1 = cw1 + layer * HD * HD;
    for (int i = tid; i < HD * HD; i += blockDim.x) { sW2[i] = w2[i]; sC1[i] = c1[i]; }
    for (int i = tid; i < HD; i += blockDim.x) {
        sC2[i] = cw2[layer * HD + i];
        sB1[i] = eb1[layer * HD + i];
        sB2[i] = eb2[layer * HD + i];
        sCB1[i] = cb1[layer * HD + i];
    }
    __syncthreads();
    float cb2v = cb2[layer];

    int lane = tid & 31;
    int wl = tid >> 5;
    float* s_in = sbuf + wl * (MIN_PAD + HD);
    float* s_m1 = s_in + MIN_PAD;
    if (lane < 3) s_in[133 + lane] = 0.0f;   // permanent zero pad

    int warp = (blockIdx.x * blockDim.x + tid) >> 5;
    int nwarp = (gridDim.x * blockDim.x) >> 5;
    int j0 = lane * 2;

    for (int e = warp; e < NE; e += nwarp) {
        int src = ei[e];
        int dst = ei[NE + e];
        const float* hdp = g_h + dst * HD;
        const float* hsp = g_h + src * HD;
        // m_in = [h[dst], h[src], d2, edge_attr]
        float2 v;
        v = *(const float2*)&hdp[j0]; s_in[j0] = v.x; s_in[j0 + 1] = v.y;
        v = *(const float2*)&hsp[j0]; s_in[64 + j0] = v.x; s_in[65 + j0] = v.y;
        float rx = g_pos[dst * 3 + 0] - g_pos[src * 3 + 0];
        float ry = g_pos[dst * 3 + 1] - g_pos[src * 3 + 1];
        float rz = g_pos[dst * 3 + 2] - g_pos[src * 3 + 2];
        float d2 = rx * rx + ry * ry + rz * rz;
        if (lane == 0) s_in[128] = d2;
        if (lane < 4) s_in[129 + lane] = ea[e * 4 + lane];
        __syncwarp();

        // GEMM1: [133] x [133,64] -> silu
        float a0 = sB1[j0], a1 = sB1[j0 + 1];
#pragma unroll 4
        for (int k = 0; k < MIN_PAD; k += 4) {
            float4 s = *(const float4*)&s_in[k];
            float2 w;
            w = *(const float2*)&sW1[(k + 0) * HD + j0]; a0 += s.x * w.x; a1 += s.x * w.y;
            w = *(const float2*)&sW1[(k + 1) * HD + j0]; a0 += s.y * w.x; a1 += s.y * w.y;
            w = *(const float2*)&sW1[(k + 2) * HD + j0]; a0 += s.z * w.x; a1 += s.z * w.y;
            w = *(const float2*)&sW1[(k + 3) * HD + j0]; a0 += s.w * w.x; a1 += s.w * w.y;
        }
        s_m1[j0] = silu_f(a0);
        s_m1[j0 + 1] = silu_f(a1);
        __syncwarp();

        // GEMM2: [64] x [64,64] -> silu = message m
        float b0 = sB2[j0], b1 = sB2[j0 + 1];
#pragma unroll 4
        for (int k = 0; k < HD; k += 4) {
            float4 s = *(const float4*)&s_m1[k];
            float2 w;
            w = *(const float2*)&sW2[(k + 0) * HD + j0]; b0 += s.x * w.x; b1 += s.x * w.y;
            w = *(const float2*)&sW2[(k + 1) * HD + j0]; b0 += s.y * w.x; b1 += s.y * w.y;
            w = *(const float2*)&sW2[(k + 2) * HD + j0]; b0 += s.z * w.x; b1 += s.z * w.y;
            w = *(const float2*)&sW2[(k + 3) * HD + j0]; b0 += s.w * w.x; b1 += s.w * w.y;
        }
        float m0 = silu_f(b0), m1v = silu_f(b1);
        __syncwarp();                 // all lanes done with s_in (GEMM1) long ago; reuse for m
        s_in[j0] = m0;
        s_in[j0 + 1] = m1v;
        __syncwarp();

        // coord MLP: c = silu(m @ cw1 + cb1) @ cw2 + cb2
        float c0 = sCB1[j0], c1v = sCB1[j0 + 1];
#pragma unroll 4
        for (int k = 0; k < HD; k += 4) {
            float4 s = *(const float4*)&s_in[k];
            float2 w;
            w = *(const float2*)&sC1[(k + 0) * HD + j0]; c0 += s.x * w.x; c1v += s.x * w.y;
            w = *(const float2*)&sC1[(k + 1) * HD + j0]; c0 += s.y * w.x; c1v += s.y * w.y;
            w = *(const float2*)&sC1[(k + 2) * HD + j0]; c0 += s.z * w.x; c1v += s.z * w.y;
            w = *(const float2*)&sC1[(k + 3) * HD + j0]; c0 += s.w * w.x; c1v += s.w * w.y;
        }
        float part = silu_f(c0) * sC2[j0] + silu_f(c1v) * sC2[j0 + 1];
#pragma unroll
        for (int o = 16; o > 0; o >>= 1) part += __shfl_xor_sync(0xffffffff, part, o);
        float c = part + cb2v;

        atomicAdd(&g_agg[dst * HD + j0], m0);
        atomicAdd(&g_agg[dst * HD + j0 + 1], m1v);
        if (lane == 0) {
            atomicAdd(&g_pacc[dst * 3 + 0], rx * c);
            atomicAdd(&g_pacc[dst * 3 + 1], ry * c);
            atomicAdd(&g_pacc[dst * 3 + 2], rz * c);
        }
        __syncwarp();                 // s_in reads done before next iteration overwrites
    }
}

// ---------------- node kernel: pos += pacc/deg; h += MLP(cat[h, agg]) ----------------
#define NODE_SMEM_F (2 * HD * HD + HD * HD + 2 * HD + 8 * (2 * HD + HD))
#define NODE_SMEM_B (NODE_SMEM_F * 4)

__global__ void node_kernel(const float* __restrict__ nw1, const float* __restrict__ nb1,
                            const float* __restrict__ nw2, const float* __restrict__ nb2,
                            int layer) {
    extern __shared__ float sm[];
    float* sW1 = sm;                 // 8192  (nw1: [128,64])
    float* sW2 = sW1 + 2 * HD * HD;  // 4096
    float* sB1 = sW2 + HD * HD;
    float* sB2 = sB1 + HD;
    float* sbuf = sB2 + HD;          // per warp: 128 + 64

    int tid = threadIdx.x;
    const float* w1 = nw1 + layer * 2 * HD * HD;
    for (int i = tid; i < 2 * HD * HD; i += blockDim.x) sW1[i] = w1[i];
    const float* w2 = nw2 + layer * HD * HD;
    for (int i = tid; i < HD * HD; i += blockDim.x) sW2[i] = w2[i];
    for (int i = tid; i < HD; i += blockDim.x) {
        sB1[i] = nb1[layer * HD + i];
        sB2[i] = nb2[layer * HD + i];
    }
    __syncthreads();

    int lane = tid & 31;
    int wl = tid >> 5;
    float* s_in = sbuf + wl * (3 * HD);
    float* s_mid = s_in + 2 * HD;
    int warp = (blockIdx.x * blockDim.x + tid) >> 5;
    int nwarp = (gridDim.x * blockDim.x) >> 5;
    int j0 = lane * 2;

    for (int n = warp; n < NN; n += nwarp) {
        float2 hv = *(const float2*)&g_h[n * HD + j0];
        float2 av = *(const float2*)&g_agg[n * HD + j0];
        s_in[j0] = hv.x; s_in[j0 + 1] = hv.y;
        s_in[2 * HD - HD + j0] = av.x;  // s_in[64 + j0]
        s_in[2 * HD - HD + j0 + 1] = av.y;
        if (lane < 3) {
            float d = g_deg[n];
            if (d < 1.0f) d = 1.0f;
            g_pos[n * 3 + lane] += g_pacc[n * 3 + lane] / d;
        }
        __syncwarp();

        float a0 = sB1[j0], a1 = sB1[j0 + 1];
#pragma unroll 4
        for (int k = 0; k < 2 * HD; k += 4) {
            float4 s = *(const float4*)&s_in[k];
            float2 w;
            w = *(const float2*)&sW1[(k + 0) * HD + j0]; a0 += s.x * w.x; a1 += s.x * w.y;
            w = *(const float2*)&sW1[(k + 1) * HD + j0]; a0 += s.y * w.x; a1 += s.y * w.y;
            w = *(const float2*)&sW1[(k + 2) * HD + j0]; a0 += s.z * w.x; a1 += s.z * w.y;
            w = *(const float2*)&sW1[(k + 3) * HD + j0]; a0 += s.w * w.x; a1 += s.w * w.y;
        }
        s_mid[j0] = silu_f(a0);
        s_mid[j0 + 1] = silu_f(a1);
        __syncwarp();

        float b0 = sB2[j0], b1 = sB2[j0 + 1];
#pragma unroll 4
        for (int k = 0; k < HD; k += 4) {
            float4 s = *(const float4*)&s_mid[k];
            float2 w;
            w = *(const float2*)&sW2[(k + 0) * HD + j0]; b0 += s.x * w.x; b1 += s.x * w.y;
            w = *(const float2*)&sW2[(k + 1) * HD + j0]; b0 += s.y * w.x; b1 += s.y * w.y;
            w = *(const float2*)&sW2[(k + 2) * HD + j0]; b0 += s.z * w.x; b1 += s.z * w.y;
            w = *(const float2*)&sW2[(k + 3) * HD + j0]; b0 += s.w * w.x; b1 += s.w * w.y;
        }
        float2 outv;
        outv.x = hv.x + b0;
        outv.y = hv.y + b1;
        *(float2*)&g_h[n * HD + j0] = outv;
        __syncwarp();
    }
}

// ---------------- pooling ----------------
__global__ void pool_zero_kernel() {
    int i = blockIdx.x * blockDim.x + threadIdx.x;
    int st = gridDim.x * blockDim.x;
    for (int j = i; j < NG * HD; j += st) g_gsum[j] = 0.0f;
    for (int j = i; j < NG; j += st) g_gcnt[j] = 0.0f;
}

__global__ void pool_kernel(const int* __restrict__ batch) {
    int tid = threadIdx.x;
    int lane = tid & 31;
    int warp = (blockIdx.x * blockDim.x + tid) >> 5;
    int nwarp = (gridDim.x * blockDim.x) >> 5;
    for (int n = warp; n < NN; n += nwarp) {
        int b = batch[n];
        atomicAdd(&g_gsum[b * HD + lane], g_h[n * HD + lane]);
        atomicAdd(&g_gsum[b * HD + 32 + lane], g_h[n * HD + 32 + lane]);
        if (lane == 0) atomicAdd(&g_gcnt[b], 1.0f);
    }
}

// ---------------- per-graph: pre-MLP, 4-qubit circuit, post-MLP ----------------
__global__ void final_kernel(const float* __restrict__ prew, const float* __restrict__ preb,
                             const float* __restrict__ qw,
                             const float* __restrict__ pw1, const float* __restrict__ pb1,
                             const float* __restrict__ pw2, const float* __restrict__ pb2,
                             float* __restrict__ out) {
    int g = threadIdx.x;
    if (g >= NG) return;
    float cnt = g_gcnt[g];
    if (cnt < 1.0f) cnt = 1.0f;
    float qin[4];
    for (int q = 0; q < 4; q++) qin[q] = preb[q];
    for (int k = 0; k < HD; k++) {
        float gv = g_gsum[g * HD + k] / cnt;
        for (int q = 0; q < 4; q++) qin[q] += gv * prew[k * 4 + q];
    }

    float pr[16], pi[16];
    for (int i = 0; i < 16; i++) { pr[i] = 0.0f; pi[i] = 0.0f; }
    pr[0] = 1.0f;

    // RX(qin[q]) on each qubit (qubit 0 = MSB, stride 8>>q)
    for (int q = 0; q < 4; q++) {
        int s = 8 >> q;
        float ch = cosf(qin[q] * 0.5f);
        float sh = sinf(qin[q] * 0.5f);
        for (int i = 0; i < 16; i++) {
            if (i & s) continue;
            int j = i | s;
            float ar = pr[i], ai = pi[i], br = pr[j], bi = pi[j];
            pr[i] = ch * ar + sh * bi;  pi[i] = ch * ai - sh * br;
            pr[j] = ch * br + sh * ai;  pi[j] = ch * bi - sh * ar;
        }
    }
    // 2 layers of RY + ring CNOT
    for (int l = 0; l < 2; l++) {
        for (int q = 0; q < 4; q++) {
            int s = 8 >> q;
            float ch = cosf(qw[l * 4 + q] * 0.5f);
            float sh = sinf(qw[l * 4 + q] * 0.5f);
            for (int i = 0; i < 16; i++) {
                if (i & s) continue;
                int j = i | s;
                float ar = pr[i], ai = pi[i], br = pr[j], bi = pi[j];
                pr[i] = ch * ar - sh * br;  pi[i] = ch * ai - sh * bi;
                pr[j] = sh * ar + ch * br;  pi[j] = sh * ai + ch * bi;
            }
        }
        for (int q = 0; q < 4; q++) {
            int cs = 8 >> q;
            int ts = 8 >> ((q + 1) & 3);
            for (int i = 0; i < 16; i++) {
                if ((i & cs) && !(i & ts)) {
                    int j = i | ts;
                    float t;
                    t = pr[i]; pr[i] = pr[j]; pr[j] = t;
                    t = pi[i]; pi[i] = pi[j]; pi[j] = t;
                }
            }
        }
    }
    float qo[4] = {0.0f, 0.0f, 0.0f, 0.0f};
    for (int i = 0; i < 16; i++) {
        float p = pr[i] * pr[i] + pi[i] * pi[i];
        for (int q = 0; q < 4; q++) qo[q] += (i & (8 >> q)) ? -p : p;
    }

    float acc = pb2[0];
    for (int j = 0; j < HD; j++) {
        float t = pb1[j];
        for (int q = 0; q < 4; q++) t += qo[q] * pw1[q * HD + j];
        acc += silu_f(t) * pw2[j];
    }
    out[g] = acc;
}

// ---------------- launch ----------------
extern "C" void kernel_launch(void* const* d_in, const int* in_sizes, int n_in,
                              void* d_out, int out_size) {
    const int* nt = (const int*)d_in[0];
    const float* pos = (const float*)d_in[1];
    const int* ei = (const int*)d_in[2];
    const float* ea = (const float*)d_in[3];
    const int* batch = (const int*)d_in[4];
    const float* emb = (const float*)d_in[5];
    const float* ew1 = (const float*)d_in[6];
    const float* eb1 = (const float*)d_in[7];
    const float* ew2 = (const float*)d_in[8];
    const float* eb2 = (const float*)d_in[9];
    const float* cw1 = (const float*)d_in[10];
    const float* cb1 = (const float*)d_in[11];
    const float* cw2 = (const float*)d_in[12];
    const float* cb2 = (const float*)d_in[13];
    const float* nw1 = (const float*)d_in[14];
    const float* nb1 = (const float*)d_in[15];
    const float* nw2 = (const float*)d_in[16];
    const float* nb2 = (const float*)d_in[17];
    const float* prew = (const float*)d_in[18];
    const float* preb = (const float*)d_in[19];
    const float* qw = (const float*)d_in[20];
    const float* pw1 = (const float*)d_in[21];
    const float* pb1 = (const float*)d_in[22];
    const float* pw2 = (const float*)d_in[23];
    const float* pb2 = (const float*)d_in[24];
    float* out = (float*)d_out;

    cudaFuncSetAttribute(edge_kernel, cudaFuncAttributeMaxDynamicSharedMemorySize, EDGE_SMEM_B);
    cudaFuncSetAttribute(node_kernel, cudaFuncAttributeMaxDynamicSharedMemorySize, NODE_SMEM_B);

    init_kernel<<<512, 256>>>(nt, emb, pos);
    deg_kernel<<<512, 256>>>(ei);
    for (int l = 0; l < NL; l++) {
        zero_layer_kernel<<<512, 256>>>();
        edge_kernel<<<296, 256, EDGE_SMEM_B>>>(ei, ea, ew1, eb1, ew2, eb2,
                                               cw1, cb1, cw2, cb2, l);
        node_kernel<<<296, 256, NODE_SMEM_B>>>(nw1, nb1, nw2, nb2, l);
    }
    pool_zero_kernel<<<64, 256>>>();
    pool_kernel<<<512, 256>>>(batch);
    final_kernel<<<1, 128>>>(prew, preb, qw, pw1, pb1, pw2, pb2, out);
}

// round 4
// speedup vs baseline: 1.5700x; 1.5700x over previous
#include <cuda_runtime.h>
#include <math.h>

#define NN 50000
#define NE 800000
#define HD 64
#define NG 128
#define NL 3
#define MIN_D 133     // 2H + 1 + edge_dim(4)
#define MIN_PAD 136
#define NTILE_E (NE / 32)          // 25000 exact
#define NTILE_N ((NN + 31) / 32)   // 1563

// ---------------- scratch ----------------
__device__ float g_h[NN * HD];
__device__ float g_pos[NN * 3];
__device__ float g_agg[NN * HD];
__device__ float g_pacc[NN * 3];
__device__ float g_deg[NN];
__device__ float g_gsum[NG * HD];
__device__ float g_gcnt[NG];

__device__ __forceinline__ float silu_f(float x) {
    return x / (1.0f + __expf(-x));
}

// ---------------- init ----------------
__global__ void init_kernel(const int* __restrict__ nt, const float* __restrict__ emb,
                            const float* __restrict__ pos) {
    int i = blockIdx.x * blockDim.x + threadIdx.x;
    int st = gridDim.x * blockDim.x;
    for (int j = i; j < NN * HD; j += st) g_h[j] = emb[nt[j >> 6] * HD + (j & 63)];
    for (int j = i; j < NN * 3; j += st) g_pos[j] = pos[j];
    for (int j = i; j < NN; j += st) g_deg[j] = 0.0f;
}

__global__ void deg_kernel(const int* __restrict__ ei) {
    int i = blockIdx.x * blockDim.x + threadIdx.x;
    int st = gridDim.x * blockDim.x;
    for (int e = i; e < NE; e += st) atomicAdd(&g_deg[ei[NE + e]], 1.0f);
}

__global__ void zero_layer_kernel() {
    int i = blockIdx.x * blockDim.x + threadIdx.x;
    int st = gridDim.x * blockDim.x;
    for (int j = i; j < NN * HD; j += st) g_agg[j] = 0.0f;
    for (int j = i; j < NN * 3; j += st) g_pacc[j] = 0.0f;
}

// =====================================================================
// Edge kernel: lane = edge, warp = 32-edge tile, register accumulators,
// float4 broadcast weight loads from shared, staged inputs (stride 33),
// message transpose through shared (stride 65) -> coalesced atomics.
// =====================================================================
#define EDGE_W_F (MIN_PAD * HD + HD * HD + HD * HD + 4 * HD)   // 17152
#define EDGE_SMEM_F (EDGE_W_F + 16 * 2080)                     // 50432
#define EDGE_SMEM_B (EDGE_SMEM_F * 4)                          // 201728 B

__global__ __launch_bounds__(512) void edge_kernel(
    const int* __restrict__ ei, const float* __restrict__ ea,
    const float* __restrict__ ew1, const float* __restrict__ eb1,
    const float* __restrict__ ew2, const float* __restrict__ eb2,
    const float* __restrict__ cw1, const float* __restrict__ cb1,
    const float* __restrict__ cw2, const float* __restrict__ cb2,
    int layer) {
    extern __shared__ float sm[];
    float* sW1 = sm;                         // [136][64]
    float* sW2 = sW1 + MIN_PAD * HD;         // [64][64]
    float* sC1 = sW2 + HD * HD;              // [64][64]
    float* sC2 = sC1 + HD * HD;              // [64]
    float* sB1 = sC2 + HD;
    float* sB2 = sB1 + HD;
    float* sCB1 = sB2 + HD;
    float* sbuf = sCB1 + HD;                 // per-warp 2080 floats

    int tid = threadIdx.x;
    const float* w1 = ew1 + layer * MIN_D * HD;
    for (int i = tid; i < MIN_PAD * HD; i += blockDim.x)
        sW1[i] = (i < MIN_D * HD) ? w1[i] : 0.0f;
    const float* w2 = ew2 + layer * HD * HD;
    const float* c1 = cw1 + layer * HD * HD;
    for (int i = tid; i < HD * HD; i += blockDim.x) { sW2[i] = w2[i]; sC1[i] = c1[i]; }
    for (int i = tid; i < HD; i += blockDim.x) {
        sC2[i] = cw2[layer * HD + i];
        sB1[i] = eb1[layer * HD + i];
        sB2[i] = eb2[layer * HD + i];
        sCB1[i] = cb1[layer * HD + i];
    }
    __syncthreads();
    float cb2v = cb2[layer];

    int lane = tid & 31;
    int wl = tid >> 5;
    float* buf = sbuf + wl * 2080;   // stride-33 staging region aliases stride-65 msg region

    int warp = (blockIdx.x * blockDim.x + tid) >> 5;
    int nwarp = (gridDim.x * blockDim.x) >> 5;

    for (int tile = warp; tile < NTILE_E; tile += nwarp) {
        int e = tile * 32 + lane;
        int src = ei[e];
        int dst = ei[NE + e];
        float4 eav = *(const float4*)(ea + (size_t)e * 4);
        float rx = g_pos[dst * 3 + 0] - g_pos[src * 3 + 0];
        float ry = g_pos[dst * 3 + 1] - g_pos[src * 3 + 1];
        float rz = g_pos[dst * 3 + 2] - g_pos[src * 3 + 2];
        float d2 = rx * rx + ry * ry + rz * rz;

        float acc[64];
#pragma unroll
        for (int j = 0; j < 64; j++) acc[j] = sB1[j];

        // -------- GEMM1: K chunks of 32 with LDG->reg prefetch pipeline --------
        float v[32];
#pragma unroll
        for (int e2 = 0; e2 < 32; e2++) {
            int row = __shfl_sync(0xffffffffu, dst, e2);
            v[e2] = g_h[row * 64 + lane];
        }
#pragma unroll
        for (int c = 0; c < 4; c++) {
            __syncwarp();            // prior readers of buf done (prev chunk / prev tile)
#pragma unroll
            for (int e2 = 0; e2 < 32; e2++) buf[e2 * 33 + lane] = v[e2];
            __syncwarp();
            if (c < 3) {             // prefetch next chunk while computing this one
                int half = (c + 1) < 2 ? dst : src;
                int col = ((c + 1) & 1) * 32 + lane;
#pragma unroll
                for (int e2 = 0; e2 < 32; e2++) {
                    int row = __shfl_sync(0xffffffffu, half, e2);
                    v[e2] = g_h[row * 64 + col];
                }
            }
            int kb = c * 32;
#pragma unroll 2
            for (int kk = 0; kk < 32; kk++) {
                float xv = buf[lane * 33 + kk];
                const float* wr = sW1 + (kb + kk) * 64;
#pragma unroll
                for (int j4 = 0; j4 < 16; j4++) {
                    float4 w = *(const float4*)(wr + 4 * j4);
                    acc[4 * j4 + 0] += xv * w.x;
                    acc[4 * j4 + 1] += xv * w.y;
                    acc[4 * j4 + 2] += xv * w.z;
                    acc[4 * j4 + 3] += xv * w.w;
                }
            }
        }
        // tail rows k = 128..132 (d2, edge_attr); 133..135 are zero-padded
        {
            float tx0 = d2, tx1 = eav.x, tx2 = eav.y, tx3 = eav.z, tx4 = eav.w;
            float txs[5] = {tx0, tx1, tx2, tx3, tx4};
#pragma unroll
            for (int t = 0; t < 5; t++) {
                float xv = txs[t];
                const float* wr = sW1 + (128 + t) * 64;
#pragma unroll
                for (int j4 = 0; j4 < 16; j4++) {
                    float4 w = *(const float4*)(wr + 4 * j4);
                    acc[4 * j4 + 0] += xv * w.x;
                    acc[4 * j4 + 1] += xv * w.y;
                    acc[4 * j4 + 2] += xv * w.z;
                    acc[4 * j4 + 3] += xv * w.w;
                }
            }
        }

        __syncwarp();                // all GEMM1 staging reads finished
#pragma unroll
        for (int j = 0; j < 64; j++) buf[lane * 65 + j] = silu_f(acc[j]);  // m1
        __syncwarp();

        // -------- GEMM2: m = silu(m1 @ W2 + b2) --------
        float acc2[64];
#pragma unroll
        for (int j = 0; j < 64; j++) acc2[j] = sB2[j];
#pragma unroll 2
        for (int k = 0; k < 64; k++) {
            float xv = buf[lane * 65 + k];
            const float* wr = sW2 + k * 64;
#pragma unroll
            for (int j4 = 0; j4 < 16; j4++) {
                float4 w = *(const float4*)(wr + 4 * j4);
                acc2[4 * j4 + 0] += xv * w.x;
                acc2[4 * j4 + 1] += xv * w.y;
                acc2[4 * j4 + 2] += xv * w.z;
                acc2[4 * j4 + 3] += xv * w.w;
            }
        }
        __syncwarp();
#pragma unroll
        for (int j = 0; j < 64; j++) buf[lane * 65 + j] = silu_f(acc2[j]);  // m
        __syncwarp();

        // -------- coord MLP (two 32-output passes; per-lane scalar result) --------
        float part = 0.0f;
#pragma unroll
        for (int p = 0; p < 2; p++) {
            float acc3[32];
#pragma unroll
            for (int j = 0; j < 32; j++) acc3[j] = sCB1[p * 32 + j];
#pragma unroll 2
            for (int k = 0; k < 64; k++) {
                float xv = buf[lane * 65 + k];
                const float* wr = sC1 + k * 64 + p * 32;
#pragma unroll
                for (int j4 = 0; j4 < 8; j4++) {
                    float4 w = *(const float4*)(wr + 4 * j4);
                    acc3[4 * j4 + 0] += xv * w.x;
                    acc3[4 * j4 + 1] += xv * w.y;
                    acc3[4 * j4 + 2] += xv * w.z;
                    acc3[4 * j4 + 3] += xv * w.w;
                }
            }
#pragma unroll
            for (int j = 0; j < 32; j++) part += silu_f(acc3[j]) * sC2[p * 32 + j];
        }
        float cc = part + cb2v;

        atomicAdd(&g_pacc[dst * 3 + 0], rx * cc);
        atomicAdd(&g_pacc[dst * 3 + 1], ry * cc);
        atomicAdd(&g_pacc[dst * 3 + 2], rz * cc);

        // coalesced message scatter via shared transpose
#pragma unroll 4
        for (int e2 = 0; e2 < 32; e2++) {
            int drow = __shfl_sync(0xffffffffu, dst, e2);
            atomicAdd(&g_agg[drow * 64 + lane],      buf[e2 * 65 + lane]);
            atomicAdd(&g_agg[drow * 64 + 32 + lane], buf[e2 * 65 + 32 + lane]);
        }
        // loop-top __syncwarp protects buf before next tile's staging stores
    }
}

// =====================================================================
// Node kernel: same template, lane = node (contiguous rows, no shuffles)
// =====================================================================
#define NODE_W_F (2 * HD * HD + HD * HD + 2 * HD)   // 12416
#define NODE_SMEM_F (NODE_W_F + 16 * 2080)          // 45696
#define NODE_SMEM_B (NODE_SMEM_F * 4)               // 182784 B

__global__ __launch_bounds__(512) void node_kernel(
    const float* __restrict__ nw1, const float* __restrict__ nb1,
    const float* __restrict__ nw2, const float* __restrict__ nb2,
    int layer) {
    extern __shared__ float sm[];
    float* sW1 = sm;                     // [128][64]
    float* sW2 = sW1 + 2 * HD * HD;      // [64][64]
    float* sB1 = sW2 + HD * HD;
    float* sB2 = sB1 + HD;
    float* sbuf = sB2 + HD;

    int tid = threadIdx.x;
    const float* w1 = nw1 + layer * 2 * HD * HD;
    for (int i = tid; i < 2 * HD * HD; i += blockDim.x) sW1[i] = w1[i];
    const float* w2 = nw2 + layer * HD * HD;
    for (int i = tid; i < HD * HD; i += blockDim.x) sW2[i] = w2[i];
    for (int i = tid; i < HD; i += blockDim.x) {
        sB1[i] = nb1[layer * HD + i];
        sB2[i] = nb2[layer * HD + i];
    }
    __syncthreads();

    int lane = tid & 31;
    int wl = tid >> 5;
    float* buf = sbuf + wl * 2080;

    int warp = (blockIdx.x * blockDim.x + tid) >> 5;
    int nwarp = (gridDim.x * blockDim.x) >> 5;

    for (int tile = warp; tile < NTILE_N; tile += nwarp) {
        int base = tile * 32;
        int n = base + lane;
        bool valid = n < NN;

        if (valid) {
            float d = g_deg[n];
            if (d < 1.0f) d = 1.0f;
            float inv = 1.0f / d;
            g_pos[n * 3 + 0] += g_pacc[n * 3 + 0] * inv;
            g_pos[n * 3 + 1] += g_pacc[n * 3 + 1] * inv;
            g_pos[n * 3 + 2] += g_pacc[n * 3 + 2] * inv;
        }

        float acc[64];
#pragma unroll
        for (int j = 0; j < 64; j++) acc[j] = sB1[j];

        float v[32];
#pragma unroll
        for (int e2 = 0; e2 < 32; e2++) {
            int row = base + e2; if (row >= NN) row = NN - 1;
            v[e2] = g_h[row * 64 + lane];
        }
#pragma unroll
        for (int c = 0; c < 4; c++) {
            __syncwarp();
#pragma unroll
            for (int e2 = 0; e2 < 32; e2++) buf[e2 * 33 + lane] = v[e2];
            __syncwarp();
            if (c < 3) {
                const float* srcp = ((c + 1) < 2) ? g_h : g_agg;
                int col = ((c + 1) & 1) * 32 + lane;
#pragma unroll
                for (int e2 = 0; e2 < 32; e2++) {
                    int row = base + e2; if (row >= NN) row = NN - 1;
                    v[e2] = srcp[row * 64 + col];
                }
            }
            int kb = c * 32;
#pragma unroll 2
            for (int kk = 0; kk < 32; kk++) {
                float xv = buf[lane * 33 + kk];
                const float* wr = sW1 + (kb + kk) * 64;
#pragma unroll
                for (int j4 = 0; j4 < 16; j4++) {
                    float4 w = *(const float4*)(wr + 4 * j4);
                    acc[4 * j4 + 0] += xv * w.x;
                    acc[4 * j4 + 1] += xv * w.y;
                    acc[4 * j4 + 2] += xv * w.z;
                    acc[4 * j4 + 3] += xv * w.w;
                }
            }
        }

        __syncwarp();
#pragma unroll
        for (int j = 0; j < 64; j++) buf[lane * 65 + j] = silu_f(acc[j]);
        __syncwarp();

        float acc2[64];
#pragma unroll
        for (int j = 0; j < 64; j++) acc2[j] = sB2[j];
#pragma unroll 2
        for (int k = 0; k < 64; k++) {
            float xv = buf[lane * 65 + k];
            const float* wr = sW2 + k * 64;
#pragma unroll
            for (int j4 = 0; j4 < 16; j4++) {
                float4 w = *(const float4*)(wr + 4 * j4);
                acc2[4 * j4 + 0] += xv * w.x;
                acc2[4 * j4 + 1] += xv * w.y;
                acc2[4 * j4 + 2] += xv * w.z;
                acc2[4 * j4 + 3] += xv * w.w;
            }
        }
        __syncwarp();
#pragma unroll
        for (int j = 0; j < 64; j++) buf[lane * 65 + j] = acc2[j];
        __syncwarp();

        // coalesced residual update h += out
#pragma unroll 4
        for (int e2 = 0; e2 < 32; e2++) {
            int row = base + e2;
            if (row < NN) {
                g_h[row * 64 + lane]      += buf[e2 * 65 + lane];
                g_h[row * 64 + 32 + lane] += buf[e2 * 65 + 32 + lane];
            }
        }
        __syncwarp();
    }
}

// ---------------- pooling ----------------
__global__ void pool_zero_kernel() {
    int i = blockIdx.x * blockDim.x + threadIdx.x;
    int st = gridDim.x * blockDim.x;
    for (int j = i; j < NG * HD; j += st) g_gsum[j] = 0.0f;
    for (int j = i; j < NG; j += st) g_gcnt[j] = 0.0f;
}

__global__ void pool_kernel(const int* __restrict__ batch) {
    int tid = threadIdx.x;
    int lane = tid & 31;
    int warp = (blockIdx.x * blockDim.x + tid) >> 5;
    int nwarp = (gridDim.x * blockDim.x) >> 5;
    for (int n = warp; n < NN; n += nwarp) {
        int b = batch[n];
        atomicAdd(&g_gsum[b * HD + lane], g_h[n * HD + lane]);
        atomicAdd(&g_gsum[b * HD + 32 + lane], g_h[n * HD + 32 + lane]);
        if (lane == 0) atomicAdd(&g_gcnt[b], 1.0f);
    }
}

// ---------------- per-graph: pre-MLP, 4-qubit circuit, post-MLP ----------------
__global__ void final_kernel(const float* __restrict__ prew, const float* __restrict__ preb,
                             const float* __restrict__ qw,
                             const float* __restrict__ pw1, const float* __restrict__ pb1,
                             const float* __restrict__ pw2, const float* __restrict__ pb2,
                             float* __restrict__ out) {
    int g = threadIdx.x;
    if (g >= NG) return;
    float cnt = g_gcnt[g];
    if (cnt < 1.0f) cnt = 1.0f;
    float qin[4];
    for (int q = 0; q < 4; q++) qin[q] = preb[q];
    for (int k = 0; k < HD; k++) {
        float gv = g_gsum[g * HD + k] / cnt;
        for (int q = 0; q < 4; q++) qin[q] += gv * prew[k * 4 + q];
    }

    float pr[16], pi[16];
    for (int i = 0; i < 16; i++) { pr[i] = 0.0f; pi[i] = 0.0f; }
    pr[0] = 1.0f;

    for (int q = 0; q < 4; q++) {
        int s = 8 >> q;
        float ch = cosf(qin[q] * 0.5f);
        float sh = sinf(qin[q] * 0.5f);
        for (int i = 0; i < 16; i++) {
            if (i & s) continue;
            int j = i | s;
            float ar = pr[i], ai = pi[i], br = pr[j], bi = pi[j];
            pr[i] = ch * ar + sh * bi;  pi[i] = ch * ai - sh * br;
            pr[j] = ch * br + sh * ai;  pi[j] = ch * bi - sh * ar;
        }
    }
    for (int l = 0; l < 2; l++) {
        for (int q = 0; q < 4; q++) {
            int s = 8 >> q;
            float ch = cosf(qw[l * 4 + q] * 0.5f);
            float sh = sinf(qw[l * 4 + q] * 0.5f);
            for (int i = 0; i < 16; i++) {
                if (i & s) continue;
                int j = i | s;
                float ar = pr[i], ai = pi[i], br = pr[j], bi = pi[j];
                pr[i] = ch * ar - sh * br;  pi[i] = ch * ai - sh * bi;
                pr[j] = sh * ar + ch * br;  pi[j] = sh * ai + ch * bi;
            }
        }
        for (int q = 0; q < 4; q++) {
            int cs = 8 >> q;
            int ts = 8 >> ((q + 1) & 3);
            for (int i = 0; i < 16; i++) {
                if ((i & cs) && !(i & ts)) {
                    int j = i | ts;
                    float t;
                    t = pr[i]; pr[i] = pr[j]; pr[j] = t;
                    t = pi[i]; pi[i] = pi[j]; pi[j] = t;
                }
            }
        }
    }
    float qo[4] = {0.0f, 0.0f, 0.0f, 0.0f};
    for (int i = 0; i < 16; i++) {
        float p = pr[i] * pr[i] + pi[i] * pi[i];
        for (int q = 0; q < 4; q++) qo[q] += (i & (8 >> q)) ? -p : p;
    }

    float acc = pb2[0];
    for (int j = 0; j < HD; j++) {
        float t = pb1[j];
        for (int q = 0; q < 4; q++) t += qo[q] * pw1[q * HD + j];
        acc += silu_f(t) * pw2[j];
    }
    out[g] = acc;
}

// ---------------- launch ----------------
extern "C" void kernel_launch(void* const* d_in, const int* in_sizes, int n_in,
                              void* d_out, int out_size) {
    const int* nt = (const int*)d_in[0];
    const float* pos = (const float*)d_in[1];
    const int* ei = (const int*)d_in[2];
    const float* ea = (const float*)d_in[3];
    const int* batch = (const int*)d_in[4];
    const float* emb = (const float*)d_in[5];
    const float* ew1 = (const float*)d_in[6];
    const float* eb1 = (const float*)d_in[7];
    const float* ew2 = (const float*)d_in[8];
    const float* eb2 = (const float*)d_in[9];
    const float* cw1 = (const float*)d_in[10];
    const float* cb1 = (const float*)d_in[11];
    const float* cw2 = (const float*)d_in[12];
    const float* cb2 = (const float*)d_in[13];
    const float* nw1 = (const float*)d_in[14];
    const float* nb1 = (const float*)d_in[15];
    const float* nw2 = (const float*)d_in[16];
    const float* nb2 = (const float*)d_in[17];
    const float* prew = (const float*)d_in[18];
    const float* preb = (const float*)d_in[19];
    const float* qw = (const float*)d_in[20];
    const float* pw1 = (const float*)d_in[21];
    const float* pb1 = (const float*)d_in[22];
    const float* pw2 = (const float*)d_in[23];
    const float* pb2 = (const float*)d_in[24];
    float* out = (float*)d_out;

    cudaFuncSetAttribute(edge_kernel, cudaFuncAttributeMaxDynamicSharedMemorySize, EDGE_SMEM_B);
    cudaFuncSetAttribute(node_kernel, cudaFuncAttributeMaxDynamicSharedMemorySize, NODE_SMEM_B);

    init_kernel<<<512, 256>>>(nt, emb, pos);
    deg_kernel<<<512, 256>>>(ei);
    for (int l = 0; l < NL; l++) {
        zero_layer_kernel<<<512, 256>>>();
        edge_kernel<<<148, 512, EDGE_SMEM_B>>>(ei, ea, ew1, eb1, ew2, eb2,
                                               cw1, cb1, cw2, cb2, l);
        node_kernel<<<148, 512, NODE_SMEM_B>>>(nw1, nb1, nw2, nb2, l);
    }
    pool_zero_kernel<<<64, 256>>>();
    pool_kernel<<<512, 256>>>(batch);
    final_kernel<<<1, 128>>>(prew, preb, qw, pw1, pb1, pw2, pb2, out);
}

// round 10
// speedup vs baseline: 3.9825x; 2.5367x over previous
#include <cuda_runtime.h>
#include <cuda_bf16.h>
#include <math.h>

#define NN 50000
#define NE 800000
#define HD 64
#define NG 128
#define NL 3
#define MIN_D 133
#define NTILE_E (NE / 32)          // 25000
#define NTILE_N ((NN + 31) / 32)   // 1563

// ---------------- scratch ----------------
__device__ float g_h[NN * HD];
__device__ float g_pos[NN * 3];
__device__ float g_agg[NN * HD];
__device__ float g_pacc[NN * 3];
__device__ float g_deg[NN];
__device__ float g_gsum[NG * HD];
__device__ float g_gcnt[NG];

__device__ __forceinline__ float silu_f(float x) { return x / (1.0f + __expf(-x)); }

// bf16 mma m16n8k16: D(16x8,f32) += A(16x16,bf16,row) * B(16x8,bf16,col)
__device__ __forceinline__ void mma16816(float d[4], const unsigned a[4], const unsigned b[2]) {
    asm volatile(
        "mma.sync.aligned.m16n8k16.row.col.f32.bf16.bf16.f32 "
        "{%0,%1,%2,%3},{%4,%5,%6,%7},{%8,%9},{%0,%1,%2,%3};\n"
        : "+f"(d[0]), "+f"(d[1]), "+f"(d[2]), "+f"(d[3])
        : "r"(a[0]), "r"(a[1]), "r"(a[2]), "r"(a[3]), "r"(b[0]), "r"(b[1]));
}

__device__ __forceinline__ void split_store(float v, __nv_bfloat16* ph, __nv_bfloat16* pl) {
    __nv_bfloat16 h = __float2bfloat16(v);
    *ph = h;
    *pl = __float2bfloat16(v - __bfloat162float(h));
}

// split a float2 into packed hi/lo bf16x2 words
__device__ __forceinline__ void split2(float2 v, unsigned& hw, unsigned& lw) {
    __nv_bfloat162 h2, l2;
    h2.x = __float2bfloat16(v.x); l2.x = __float2bfloat16(v.x - __bfloat162float(h2.x));
    h2.y = __float2bfloat16(v.y); l2.y = __float2bfloat16(v.y - __bfloat162float(h2.y));
    hw = *(unsigned*)&h2;
    lw = *(unsigned*)&l2;
}

// One k-tile (16 features) of a 32x64 = A(32xK) * W(Kx64) GEMM, 3-term split.
// xh/xl: staged A hi/lo, 36-word rows. wh/wl: Wt[n][k] bf16, ws-word rows.
__device__ __forceinline__ void gemm_kt(float (*acc)[4],
                                        const unsigned* __restrict__ xh, const unsigned* __restrict__ xl,
                                        const unsigned* __restrict__ wh, const unsigned* __restrict__ wl,
                                        int ws, int ktA, int ktW, int g, int c) {
    unsigned bh[8][2], bl[8][2];
#pragma unroll
    for (int nt = 0; nt < 8; nt++) {
        int idx = (nt * 8 + g) * ws + ktW * 8 + c;
        bh[nt][0] = wh[idx]; bh[nt][1] = wh[idx + 4];
        bl[nt][0] = wl[idx]; bl[nt][1] = wl[idx + 4];
    }
#pragma unroll
    for (int mt = 0; mt < 2; mt++) {
        int ra = (g + 16 * mt) * 36 + ktA * 8 + c;
        int rb = ra + 8 * 36;
        unsigned ah[4] = {xh[ra], xh[rb], xh[ra + 4], xh[rb + 4]};
        unsigned al[4] = {xl[ra], xl[rb], xl[ra + 4], xl[rb + 4]};
#pragma unroll
        for (int nt = 0; nt < 8; nt++) {
            mma16816(acc[mt * 8 + nt], ah, bh[nt]);
            mma16816(acc[mt * 8 + nt], ah, bl[nt]);
            mma16816(acc[mt * 8 + nt], al, bh[nt]);
        }
    }
}

// silu (optional) + hi/lo split + store fragments back to staging (36-word rows)
__device__ __forceinline__ void act_store(float (*acc)[4], unsigned* oh, unsigned* ol,
                                          int g, int c, bool dosilu) {
#pragma unroll
    for (int mt = 0; mt < 2; mt++)
#pragma unroll
        for (int nt = 0; nt < 8; nt++) {
            float v0 = acc[mt * 8 + nt][0], v1 = acc[mt * 8 + nt][1];
            float v2 = acc[mt * 8 + nt][2], v3 = acc[mt * 8 + nt][3];
            if (dosilu) { v0 = silu_f(v0); v1 = silu_f(v1); v2 = silu_f(v2); v3 = silu_f(v3); }
            unsigned h01, l01, h23, l23;
            split2(make_float2(v0, v1), h01, l01);
            split2(make_float2(v2, v3), h23, l23);
            int w0 = (g + 16 * mt) * 36 + nt * 4 + c;
            int w1 = (g + 8 + 16 * mt) * 36 + nt * 4 + c;
            oh[w0] = h01; ol[w0] = l01;
            oh[w1] = h23; ol[w1] = l23;
        }
}

// ---------------- init ----------------
__global__ void init_kernel(const int* __restrict__ nt, const float* __restrict__ emb,
                            const float* __restrict__ pos) {
    int i = blockIdx.x * blockDim.x + threadIdx.x;
    int st = gridDim.x * blockDim.x;
    for (int j = i; j < NN * HD; j += st) g_h[j] = emb[nt[j >> 6] * HD + (j & 63)];
    for (int j = i; j < NN * 3; j += st) g_pos[j] = pos[j];
    for (int j = i; j < NN; j += st) g_deg[j] = 0.0f;
}

__global__ void deg_kernel(const int* __restrict__ ei) {
    int i = blockIdx.x * blockDim.x + threadIdx.x;
    int st = gridDim.x * blockDim.x;
    for (int e = i; e < NE; e += st) atomicAdd(&g_deg[ei[NE + e]], 1.0f);
}

__global__ void zero_layer_kernel() {
    int i = blockIdx.x * blockDim.x + threadIdx.x;
    int st = gridDim.x * blockDim.x;
    for (int j = i; j < NN * HD; j += st) g_agg[j] = 0.0f;
    for (int j = i; j < NN * 3; j += st) g_pacc[j] = 0.0f;
}

// =====================================================================
// Edge kernel (tensor-core path)
// =====================================================================
#define EDGE_SMEM_B (76800 + 16 * 9216)   // 224256

__global__ __launch_bounds__(512) void edge_kernel(
    const int* __restrict__ ei, const float* __restrict__ ea,
    const float* __restrict__ ew1, const float* __restrict__ eb1,
    const float* __restrict__ ew2, const float* __restrict__ eb2,
    const float* __restrict__ cw1, const float* __restrict__ cb1,
    const float* __restrict__ cw2, const float* __restrict__ cb2,
    int layer) {
    extern __shared__ char smb[];
    __nv_bfloat16* w1h_e = (__nv_bfloat16*)(smb + 0);
    __nv_bfloat16* w1l_e = (__nv_bfloat16*)(smb + 19456);
    __nv_bfloat16* w2h_e = (__nv_bfloat16*)(smb + 38912);
    __nv_bfloat16* w2l_e = (__nv_bfloat16*)(smb + 48128);
    __nv_bfloat16* c1h_e = (__nv_bfloat16*)(smb + 57344);
    __nv_bfloat16* c1l_e = (__nv_bfloat16*)(smb + 66560);
    float* sB1 = (float*)(smb + 75776);
    float* sB2 = sB1 + 64;
    float* sCB1 = sB2 + 64;
    float* sC2 = sCB1 + 64;

    int tid = threadIdx.x;
    const float* w1g = ew1 + layer * MIN_D * HD;
    for (int i = tid; i < 64 * 152; i += blockDim.x) {
        int n = i / 152, k = i % 152;
        float v = (k < MIN_D) ? w1g[k * 64 + n] : 0.0f;
        split_store(v, w1h_e + n * 152 + k, w1l_e + n * 152 + k);
    }
    const float* w2g = ew2 + layer * 64 * 64;
    const float* c1g = cw1 + layer * 64 * 64;
    for (int i = tid; i < 64 * 72; i += blockDim.x) {
        int n = i / 72, k = i % 72;
        float v2 = (k < 64) ? w2g[k * 64 + n] : 0.0f;
        float vc = (k < 64) ? c1g[k * 64 + n] : 0.0f;
        split_store(v2, w2h_e + n * 72 + k, w2l_e + n * 72 + k);
        split_store(vc, c1h_e + n * 72 + k, c1l_e + n * 72 + k);
    }
    for (int i = tid; i < 64; i += blockDim.x) {
        sB1[i] = eb1[layer * 64 + i];
        sB2[i] = eb2[layer * 64 + i];
        sCB1[i] = cb1[layer * 64 + i];
        sC2[i] = cw2[layer * 64 + i];
    }
    __syncthreads();
    float cb2v = cb2[layer];

    const unsigned* w1hw = (const unsigned*)w1h_e;
    const unsigned* w1lw = (const unsigned*)w1l_e;
    const unsigned* w2hw = (const unsigned*)w2h_e;
    const unsigned* w2lw = (const unsigned*)w2l_e;
    const unsigned* c1hw = (const unsigned*)c1h_e;
    const unsigned* c1lw = (const unsigned*)c1l_e;

    int lane = tid & 31;
    int wl = tid >> 5;
    int g = lane >> 2;
    int c = lane & 3;
    unsigned* bhw = (unsigned*)(smb + 76800 + wl * 9216);
    unsigned* blw = bhw + 1152;
    __nv_bfloat16* bh_e = (__nv_bfloat16*)bhw;
    __nv_bfloat16* bl_e = (__nv_bfloat16*)blw;

    int warp = (blockIdx.x * blockDim.x + tid) >> 5;
    int nwarp = (gridDim.x * blockDim.x) >> 5;

    for (int tile = warp; tile < NTILE_E; tile += nwarp) {
        int e = tile * 32 + lane;
        int src = ei[e];
        int dst = ei[NE + e];
        float4 eav = *(const float4*)(ea + (size_t)e * 4);
        float rx = g_pos[dst * 3 + 0] - g_pos[src * 3 + 0];
        float ry = g_pos[dst * 3 + 1] - g_pos[src * 3 + 1];
        float rz = g_pos[dst * 3 + 2] - g_pos[src * 3 + 2];
        float d2 = rx * rx + ry * ry + rz * rz;

        float acc[16][4];
#pragma unroll
        for (int mt = 0; mt < 2; mt++)
#pragma unroll
            for (int nt = 0; nt < 8; nt++) {
                float b0 = sB1[nt * 8 + 2 * c], b1 = sB1[nt * 8 + 2 * c + 1];
                acc[mt * 8 + nt][0] = b0; acc[mt * 8 + nt][1] = b1;
                acc[mt * 8 + nt][2] = b0; acc[mt * 8 + nt][3] = b1;
            }

        // ---- GEMM1, chunk0: h[dst] (all 64 features; lane covers cols 2l,2l+1) ----
        __syncwarp();
#pragma unroll 4
        for (int e2 = 0; e2 < 32; e2++) {
            int row = __shfl_sync(0xffffffffu, dst, e2);
            float2 v = *(const float2*)&g_h[row * 64 + 2 * lane];
            unsigned hw, lw2;
            split2(v, hw, lw2);
            bhw[e2 * 36 + lane] = hw;
            blw[e2 * 36 + lane] = lw2;
        }
        __syncwarp();
#pragma unroll
        for (int kt = 0; kt < 4; kt++)
            gemm_kt(acc, bhw, blw, w1hw, w1lw, 76, kt, kt, g, c);

        // ---- chunk1: h[src] (features 64..127) ----
        __syncwarp();
#pragma unroll 4
        for (int e2 = 0; e2 < 32; e2++) {
            int row = __shfl_sync(0xffffffffu, src, e2);
            float2 v = *(const float2*)&g_h[row * 64 + 2 * lane];
            unsigned hw, lw2;
            split2(v, hw, lw2);
            bhw[e2 * 36 + lane] = hw;
            blw[e2 * 36 + lane] = lw2;
        }
        __syncwarp();
#pragma unroll
        for (int kt = 0; kt < 4; kt++)
            gemm_kt(acc, bhw, blw, w1hw, w1lw, 76, kt, 4 + kt, g, c);

        // ---- chunk2: tail (d2, ea, zeros) = features 128..143 ----
        __syncwarp();
        {
            float ea4[4] = {eav.x, eav.y, eav.z, eav.w};
#pragma unroll
            for (int t = 0; t < 8; t++) {
                float v0 = (t == 0) ? d2 : ((t < 3) ? ea4[t * 2 - 2 + 1 - 1] : 0.0f);
                // explicit features: f0=d2, f1..f4=ea, f5..f15=0
            }
            // write 16 tail features as 8 packed words per row (this lane's own row)
            float tf[16];
            tf[0] = d2; tf[1] = ea4[0]; tf[2] = ea4[1]; tf[3] = ea4[2]; tf[4] = ea4[3];
#pragma unroll
            for (int t = 5; t < 16; t++) tf[t] = 0.0f;
#pragma unroll
            for (int t = 0; t < 8; t++) {
                unsigned hw, lw2;
                split2(make_float2(tf[2 * t], tf[2 * t + 1]), hw, lw2);
                bhw[lane * 36 + t] = hw;
                blw[lane * 36 + t] = lw2;
            }
        }
        __syncwarp();
        gemm_kt(acc, bhw, blw, w1hw, w1lw, 76, 0, 8, g, c);

        // ---- m1 = silu(acc); stage; GEMM2 ----
        __syncwarp();
        act_store(acc, bhw, blw, g, c, true);
        __syncwarp();

        float acc2[16][4];
#pragma unroll
        for (int mt = 0; mt < 2; mt++)
#pragma unroll
            for (int nt = 0; nt < 8; nt++) {
                float b0 = sB2[nt * 8 + 2 * c], b1 = sB2[nt * 8 + 2 * c + 1];
                acc2[mt * 8 + nt][0] = b0; acc2[mt * 8 + nt][1] = b1;
                acc2[mt * 8 + nt][2] = b0; acc2[mt * 8 + nt][3] = b1;
            }
#pragma unroll
        for (int kt = 0; kt < 4; kt++)
            gemm_kt(acc2, bhw, blw, w2hw, w2lw, 36, kt, kt, g, c);

        // ---- m = silu(acc2); stage; coord GEMM ----
        __syncwarp();
        act_store(acc2, bhw, blw, g, c, true);
        __syncwarp();

        float acc3[16][4];
#pragma unroll
        for (int mt = 0; mt < 2; mt++)
#pragma unroll
            for (int nt = 0; nt < 8; nt++) {
                float b0 = sCB1[nt * 8 + 2 * c], b1 = sCB1[nt * 8 + 2 * c + 1];
                acc3[mt * 8 + nt][0] = b0; acc3[mt * 8 + nt][1] = b1;
                acc3[mt * 8 + nt][2] = b0; acc3[mt * 8 + nt][3] = b1;
            }
#pragma unroll
        for (int kt = 0; kt < 4; kt++)
            gemm_kt(acc3, bhw, blw, c1hw, c1lw, 36, kt, kt, g, c);

        // coord scalar: cc[edge] = sum_col silu(acc3) * sC2[col] + cb2
        float p0 = 0.f, p1 = 0.f, p2 = 0.f, p3 = 0.f;
#pragma unroll
        for (int nt = 0; nt < 8; nt++) {
            float w0 = sC2[nt * 8 + 2 * c], w1 = sC2[nt * 8 + 2 * c + 1];
            p0 += silu_f(acc3[nt][0]) * w0 + silu_f(acc3[nt][1]) * w1;
            p1 += silu_f(acc3[nt][2]) * w0 + silu_f(acc3[nt][3]) * w1;
            p2 += silu_f(acc3[8 + nt][0]) * w0 + silu_f(acc3[8 + nt][1]) * w1;
            p3 += silu_f(acc3[8 + nt][2]) * w0 + silu_f(acc3[8 + nt][3]) * w1;
        }
        p0 += __shfl_xor_sync(0xffffffffu, p0, 1); p0 += __shfl_xor_sync(0xffffffffu, p0, 2);
        p1 += __shfl_xor_sync(0xffffffffu, p1, 1); p1 += __shfl_xor_sync(0xffffffffu, p1, 2);
        p2 += __shfl_xor_sync(0xffffffffu, p2, 1); p2 += __shfl_xor_sync(0xffffffffu, p2, 2);
        p3 += __shfl_xor_sync(0xffffffffu, p3, 1); p3 += __shfl_xor_sync(0xffffffffu, p3, 2);
        int srcl = (lane & 7) * 4;
        float t0 = __shfl_sync(0xffffffffu, p0, srcl);
        float t1 = __shfl_sync(0xffffffffu, p1, srcl);
        float t2 = __shfl_sync(0xffffffffu, p2, srcl);
        float t3 = __shfl_sync(0xffffffffu, p3, srcl);
        int q = lane >> 3;
        float cc = (q == 0) ? t0 : ((q == 1) ? t1 : ((q == 2) ? t2 : t3));
        cc += cb2v;

        atomicAdd(&g_pacc[dst * 3 + 0], rx * cc);
        atomicAdd(&g_pacc[dst * 3 + 1], ry * cc);
        atomicAdd(&g_pacc[dst * 3 + 2], rz * cc);

        // message scatter (m = hi + lo, staged) — coalesced atomics
#pragma unroll 4
        for (int e2 = 0; e2 < 32; e2++) {
            int drow = __shfl_sync(0xffffffffu, dst, e2);
            float v0 = __bfloat162float(bh_e[e2 * 72 + lane]) + __bfloat162float(bl_e[e2 * 72 + lane]);
            float v1 = __bfloat162float(bh_e[e2 * 72 + 32 + lane]) + __bfloat162float(bl_e[e2 * 72 + 32 + lane]);
            atomicAdd(&g_agg[drow * 64 + lane], v0);
            atomicAdd(&g_agg[drow * 64 + 32 + lane], v1);
        }
    }
}

// =====================================================================
// Node kernel (tensor-core path)
// =====================================================================
#define NODE_SMEM_B (53760 + 16 * 9216)   // 201216

__global__ __launch_bounds__(512) void node_kernel(
    const float* __restrict__ nw1, const float* __restrict__ nb1,
    const float* __restrict__ nw2, const float* __restrict__ nb2,
    int layer) {
    extern __shared__ char smb[];
    __nv_bfloat16* w1h_e = (__nv_bfloat16*)(smb + 0);
    __nv_bfloat16* w1l_e = (__nv_bfloat16*)(smb + 17408);
    __nv_bfloat16* w2h_e = (__nv_bfloat16*)(smb + 34816);
    __nv_bfloat16* w2l_e = (__nv_bfloat16*)(smb + 44032);
    float* sB1 = (float*)(smb + 53248);
    float* sB2 = sB1 + 64;

    int tid = threadIdx.x;
    const float* w1g = nw1 + layer * 128 * 64;
    for (int i = tid; i < 64 * 136; i += blockDim.x) {
        int n = i / 136, k = i % 136;
        float v = (k < 128) ? w1g[k * 64 + n] : 0.0f;
        split_store(v, w1h_e + n * 136 + k, w1l_e + n * 136 + k);
    }
    const float* w2g = nw2 + layer * 64 * 64;
    for (int i = tid; i < 64 * 72; i += blockDim.x) {
        int n = i / 72, k = i % 72;
        float v = (k < 64) ? w2g[k * 64 + n] : 0.0f;
        split_store(v, w2h_e + n * 72 + k, w2l_e + n * 72 + k);
    }
    for (int i = tid; i < 64; i += blockDim.x) {
        sB1[i] = nb1[layer * 64 + i];
        sB2[i] = nb2[layer * 64 + i];
    }
    __syncthreads();

    const unsigned* w1hw = (const unsigned*)w1h_e;
    const unsigned* w1lw = (const unsigned*)w1l_e;
    const unsigned* w2hw = (const unsigned*)w2h_e;
    const unsigned* w2lw = (const unsigned*)w2l_e;

    int lane = tid & 31;
    int wl = tid >> 5;
    int g = lane >> 2;
    int c = lane & 3;
    unsigned* bhw = (unsigned*)(smb + 53760 + wl * 9216);
    unsigned* blw = bhw + 1152;

    int warp = (blockIdx.x * blockDim.x + tid) >> 5;
    int nwarp = (gridDim.x * blockDim.x) >> 5;

    for (int tile = warp; tile < NTILE_N; tile += nwarp) {
        int base = tile * 32;
        int n = base + lane;

        if (n < NN) {
            float d = g_deg[n];
            if (d < 1.0f) d = 1.0f;
            float inv = 1.0f / d;
            g_pos[n * 3 + 0] += g_pacc[n * 3 + 0] * inv;
            g_pos[n * 3 + 1] += g_pacc[n * 3 + 1] * inv;
            g_pos[n * 3 + 2] += g_pacc[n * 3 + 2] * inv;
        }

        float acc[16][4];
#pragma unroll
        for (int mt = 0; mt < 2; mt++)
#pragma unroll
            for (int nt = 0; nt < 8; nt++) {
                float b0 = sB1[nt * 8 + 2 * c], b1 = sB1[nt * 8 + 2 * c + 1];
                acc[mt * 8 + nt][0] = b0; acc[mt * 8 + nt][1] = b1;
                acc[mt * 8 + nt][2] = b0; acc[mt * 8 + nt][3] = b1;
            }

        // chunk0: h (all 64 features per row)
        __syncwarp();
#pragma unroll 4
        for (int e2 = 0; e2 < 32; e2++) {
            int row = base + e2; if (row >= NN) row = NN - 1;
            float2 v = *(const float2*)&g_h[row * 64 + 2 * lane];
            unsigned hw, lw2;
            split2(v, hw, lw2);
            bhw[e2 * 36 + lane] = hw;
            blw[e2 * 36 + lane] = lw2;
        }
        __syncwarp();
#pragma unroll
        for (int kt = 0; kt < 4; kt++)
            gemm_kt(acc, bhw, blw, w1hw, w1lw, 68, kt, kt, g, c);

        // chunk1: agg
        __syncwarp();
#pragma unroll 4
        for (int e2 = 0; e2 < 32; e2++) {
            int row = base + e2; if (row >= NN) row = NN - 1;
            float2 v = *(const float2*)&g_agg[row * 64 + 2 * lane];
            unsigned hw, lw2;
            split2(v, hw, lw2);
            bhw[e2 * 36 + lane] = hw;
            blw[e2 * 36 + lane] = lw2;
        }
        __syncwarp();
#pragma unroll
        for (int kt = 0; kt < 4; kt++)
            gemm_kt(acc, bhw, blw, w1hw, w1lw, 68, kt, 4 + kt, g, c);

        // m1 = silu; stage; GEMM2
        __syncwarp();
        act_store(acc, bhw, blw, g, c, true);
        __syncwarp();

        float acc2[16][4];
#pragma unroll
        for (int mt = 0; mt < 2; mt++)
#pragma unroll
            for (int nt = 0; nt < 8; nt++) {
                float b0 = sB2[nt * 8 + 2 * c], b1 = sB2[nt * 8 + 2 * c + 1];
                acc2[mt * 8 + nt][0] = b0; acc2[mt * 8 + nt][1] = b1;
                acc2[mt * 8 + nt][2] = b0; acc2[mt * 8 + nt][3] = b1;
            }
#pragma unroll
        for (int kt = 0; kt < 4; kt++)
            gemm_kt(acc2, bhw, blw, w2hw, w2lw, 36, kt, kt, g, c);

        // residual h += out, directly from fragments (float2 per pair)
#pragma unroll
        for (int mt = 0; mt < 2; mt++)
#pragma unroll
            for (int nt = 0; nt < 8; nt++) {
                int r0 = base + g + 16 * mt;
                int r1 = r0 + 8;
                int col = nt * 8 + 2 * c;
                if (r0 < NN) {
                    float2* p = (float2*)&g_h[r0 * 64 + col];
                    float2 o = *p;
                    o.x += acc2[mt * 8 + nt][0]; o.y += acc2[mt * 8 + nt][1];
                    *p = o;
                }
                if (r1 < NN) {
                    float2* p = (float2*)&g_h[r1 * 64 + col];
                    float2 o = *p;
                    o.x += acc2[mt * 8 + nt][2]; o.y += acc2[mt * 8 + nt][3];
                    *p = o;
                }
            }
    }
}

// ---------------- pooling ----------------
__global__ void pool_zero_kernel() {
    int i = blockIdx.x * blockDim.x + threadIdx.x;
    int st = gridDim.x * blockDim.x;
    for (int j = i; j < NG * HD; j += st) g_gsum[j] = 0.0f;
    for (int j = i; j < NG; j += st) g_gcnt[j] = 0.0f;
}

__global__ void pool_kernel(const int* __restrict__ batch) {
    int tid = threadIdx.x;
    int lane = tid & 31;
    int warp = (blockIdx.x * blockDim.x + tid) >> 5;
    int nwarp = (gridDim.x * blockDim.x) >> 5;
    for (int n = warp; n < NN; n += nwarp) {
        int b = batch[n];
        atomicAdd(&g_gsum[b * HD + lane], g_h[n * HD + lane]);
        atomicAdd(&g_gsum[b * HD + 32 + lane], g_h[n * HD + 32 + lane]);
        if (lane == 0) atomicAdd(&g_gcnt[b], 1.0f);
    }
}

// ---------------- per-graph: pre-MLP, 4-qubit circuit, post-MLP ----------------
__global__ void final_kernel(const float* __restrict__ prew, const float* __restrict__ preb,
                             const float* __restrict__ qw,
                             const float* __restrict__ pw1, const float* __restrict__ pb1,
                             const float* __restrict__ pw2, const float* __restrict__ pb2,
                             float* __restrict__ out) {
    int g = threadIdx.x;
    if (g >= NG) return;
    float cnt = g_gcnt[g];
    if (cnt < 1.0f) cnt = 1.0f;
    float qin[4];
    for (int q = 0; q < 4; q++) qin[q] = preb[q];
    for (int k = 0; k < HD; k++) {
        float gv = g_gsum[g * HD + k] / cnt;
        for (int q = 0; q < 4; q++) qin[q] += gv * prew[k * 4 + q];
    }

    float pr[16], pi[16];
    for (int i = 0; i < 16; i++) { pr[i] = 0.0f; pi[i] = 0.0f; }
    pr[0] = 1.0f;

    for (int q = 0; q < 4; q++) {
        int s = 8 >> q;
        float ch = cosf(qin[q] * 0.5f);
        float sh = sinf(qin[q] * 0.5f);
        for (int i = 0; i < 16; i++) {
            if (i & s) continue;
            int j = i | s;
            float ar = pr[i], ai = pi[i], br = pr[j], bi = pi[j];
            pr[i] = ch * ar + sh * bi;  pi[i] = ch * ai - sh * br;
            pr[j] = ch * br + sh * ai;  pi[j] = ch * bi - sh * ar;
        }
    }
    for (int l = 0; l < 2; l++) {
        for (int q = 0; q < 4; q++) {
            int s = 8 >> q;
            float ch = cosf(qw[l * 4 + q] * 0.5f);
            float sh = sinf(qw[l * 4 + q] * 0.5f);
            for (int i = 0; i < 16; i++) {
                if (i & s) continue;
                int j = i | s;
                float ar = pr[i], ai = pi[i], br = pr[j], bi = pi[j];
                pr[i] = ch * ar - sh * br;  pi[i] = ch * ai - sh * bi;
                pr[j] = sh * ar + ch * br;  pi[j] = sh * ai + ch * bi;
            }
        }
        for (int q = 0; q < 4; q++) {
            int cs = 8 >> q;
            int ts = 8 >> ((q + 1) & 3);
            for (int i = 0; i < 16; i++) {
                if ((i & cs) && !(i & ts)) {
                    int j = i | ts;
                    float t;
                    t = pr[i]; pr[i] = pr[j]; pr[j] = t;
                    t = pi[i]; pi[i] = pi[j]; pi[j] = t;
                }
            }
        }
    }
    float qo[4] = {0.0f, 0.0f, 0.0f, 0.0f};
    for (int i = 0; i < 16; i++) {
        float p = pr[i] * pr[i] + pi[i] * pi[i];
        for (int q = 0; q < 4; q++) qo[q] += (i & (8 >> q)) ? -p : p;
    }

    float acc = pb2[0];
    for (int j = 0; j < HD; j++) {
        float t = pb1[j];
        for (int q = 0; q < 4; q++) t += qo[q] * pw1[q * HD + j];
        acc += silu_f(t) * pw2[j];
    }
    out[g] = acc;
}

// ---------------- launch ----------------
extern "C" void kernel_launch(void* const* d_in, const int* in_sizes, int n_in,
                              void* d_out, int out_size) {
    const int* nt = (const int*)d_in[0];
    const float* pos = (const float*)d_in[1];
    const int* ei = (const int*)d_in[2];
    const float* ea = (const float*)d_in[3];
    const int* batch = (const int*)d_in[4];
    const float* emb = (const float*)d_in[5];
    const float* ew1 = (const float*)d_in[6];
    const float* eb1 = (const float*)d_in[7];
    const float* ew2 = (const float*)d_in[8];
    const float* eb2 = (const float*)d_in[9];
    const float* cw1 = (const float*)d_in[10];
    const float* cb1 = (const float*)d_in[11];
    const float* cw2 = (const float*)d_in[12];
    const float* cb2 = (const float*)d_in[13];
    const float* nw1 = (const float*)d_in[14];
    const float* nb1 = (const float*)d_in[15];
    const float* nw2 = (const float*)d_in[16];
    const float* nb2 = (const float*)d_in[17];
    const float* prew = (const float*)d_in[18];
    const float* preb = (const float*)d_in[19];
    const float* qw = (const float*)d_in[20];
    const float* pw1 = (const float*)d_in[21];
    const float* pb1 = (const float*)d_in[22];
    const float* pw2 = (const float*)d_in[23];
    const float* pb2 = (const float*)d_in[24];
    float* out = (float*)d_out;

    cudaFuncSetAttribute(edge_kernel, cudaFuncAttributeMaxDynamicSharedMemorySize, EDGE_SMEM_B);
    cudaFuncSetAttribute(node_kernel, cudaFuncAttributeMaxDynamicSharedMemorySize, NODE_SMEM_B);

    init_kernel<<<512, 256>>>(nt, emb, pos);
    deg_kernel<<<512, 256>>>(ei);
    for (int l = 0; l < NL; l++) {
        zero_layer_kernel<<<512, 256>>>();
        edge_kernel<<<148, 512, EDGE_SMEM_B>>>(ei, ea, ew1, eb1, ew2, eb2,
                                               cw1, cb1, cw2, cb2, l);
        node_kernel<<<148, 512, NODE_SMEM_B>>>(nw1, nb1, nw2, nb2, l);
    }
    pool_zero_kernel<<<64, 256>>>();
    pool_kernel<<<512, 256>>>(batch);
    final_kernel<<<1, 128>>>(prew, preb, qw, pw1, pb1, pw2, pb2, out);
}

// round 11
// speedup vs baseline: 4.3724x; 1.0979x over previous
#include <cuda_runtime.h>
#include <cuda_bf16.h>
#include <math.h>

#define NN 50000
#define NE 800000
#define HD 64
#define NG 128
#define NL 3
#define MIN_D 133
#define NTILE_E (NE / 32)          // 25000
#define NTILE_N ((NN + 31) / 32)   // 1563

// ---------------- scratch ----------------
__device__ float g_h[NN * HD];
__device__ unsigned g_hh[NN * 32];   // h hi, packed bf16x2 per word
__device__ unsigned g_hl[NN * 32];   // h lo
__device__ float g_pos[NN * 3];
__device__ float g_agg[NN * HD];
__device__ float g_pacc[NN * 3];
__device__ float g_deg[NN];
__device__ float g_gsum[NG * HD];
__device__ float g_gcnt[NG];

__device__ __forceinline__ float silu_f(float x) { return x / (1.0f + __expf(-x)); }

__device__ __forceinline__ void mma16816(float d[4], const unsigned* a, const unsigned* b) {
    asm volatile(
        "mma.sync.aligned.m16n8k16.row.col.f32.bf16.bf16.f32 "
        "{%0,%1,%2,%3},{%4,%5,%6,%7},{%8,%9},{%0,%1,%2,%3};\n"
        : "+f"(d[0]), "+f"(d[1]), "+f"(d[2]), "+f"(d[3])
        : "r"(a[0]), "r"(a[1]), "r"(a[2]), "r"(a[3]), "r"(b[0]), "r"(b[1]));
}

__device__ __forceinline__ void ldm4(unsigned* r, unsigned addr) {
    asm volatile("ldmatrix.sync.aligned.m8n8.x4.shared.b16 {%0,%1,%2,%3}, [%4];\n"
        : "=r"(r[0]), "=r"(r[1]), "=r"(r[2]), "=r"(r[3]) : "r"(addr));
}

__device__ __forceinline__ unsigned smem_u32(const void* p) {
    return (unsigned)__cvta_generic_to_shared(p);
}

__device__ __forceinline__ void cp16(unsigned dst, const void* src) {
    asm volatile("cp.async.cg.shared.global [%0], [%1], 16;\n" :: "r"(dst), "l"(src));
}
__device__ __forceinline__ void cp_commit() {
    asm volatile("cp.async.commit_group;\n" ::: "memory");
}
__device__ __forceinline__ void cp_wait() {
    asm volatile("cp.async.wait_all;\n" ::: "memory");
}

__device__ __forceinline__ void split_store(float v, __nv_bfloat16* ph, __nv_bfloat16* pl) {
    __nv_bfloat16 h = __float2bfloat16(v);
    *ph = h;
    *pl = __float2bfloat16(v - __bfloat162float(h));
}

__device__ __forceinline__ void split2(float2 v, unsigned& hw, unsigned& lw) {
    __nv_bfloat162 h2, l2;
    h2.x = __float2bfloat16(v.x); l2.x = __float2bfloat16(v.x - __bfloat162float(h2.x));
    h2.y = __float2bfloat16(v.y); l2.y = __float2bfloat16(v.y - __bfloat162float(h2.y));
    hw = *(unsigned*)&h2;
    lw = *(unsigned*)&l2;
}

// One 16-feature k-tile of the 32x64 GEMM, 3-term bf16 split, ldmatrix loads.
// aH/aL: per-lane A base addr (mt=0,kt=0). wH/wL: per-lane weight base (grp0,kt=0).
// wgb: weight group stride bytes (16 rows * ws * 4).
__device__ __forceinline__ void gemm_kt_lm(float (*acc)[4],
        unsigned aH, unsigned aL, unsigned wH, unsigned wL,
        int wgb, int ktA, int ktW) {
    unsigned ah0[4], ah1[4], al0[4], al1[4];
    ldm4(ah0, aH + ktA * 32);
    ldm4(ah1, aH + 2304 + ktA * 32);
    ldm4(al0, aL + ktA * 32);
    ldm4(al1, aL + 2304 + ktA * 32);
#pragma unroll
    for (int grp = 0; grp < 4; grp++) {
        unsigned bh[4], bl[4];
        ldm4(bh, wH + grp * wgb + ktW * 32);
        ldm4(bl, wL + grp * wgb + ktW * 32);
        mma16816(acc[2 * grp],     ah0, bh);     mma16816(acc[2 * grp],     ah0, bl);     mma16816(acc[2 * grp],     al0, bh);
        mma16816(acc[2 * grp + 1], ah0, bh + 2); mma16816(acc[2 * grp + 1], ah0, bl + 2); mma16816(acc[2 * grp + 1], al0, bh + 2);
        mma16816(acc[8 + 2 * grp],     ah1, bh);     mma16816(acc[8 + 2 * grp],     ah1, bl);     mma16816(acc[8 + 2 * grp],     al1, bh);
        mma16816(acc[8 + 2 * grp + 1], ah1, bh + 2); mma16816(acc[8 + 2 * grp + 1], ah1, bl + 2); mma16816(acc[8 + 2 * grp + 1], al1, bh + 2);
    }
}

// silu (optional) + hi/lo split + store fragments to staging (36-word rows)
__device__ __forceinline__ void act_store(float (*acc)[4], unsigned* oh, unsigned* ol,
                                          int g, int c, bool dosilu) {
#pragma unroll
    for (int mt = 0; mt < 2; mt++)
#pragma unroll
        for (int nt = 0; nt < 8; nt++) {
            float v0 = acc[mt * 8 + nt][0], v1 = acc[mt * 8 + nt][1];
            float v2 = acc[mt * 8 + nt][2], v3 = acc[mt * 8 + nt][3];
            if (dosilu) { v0 = silu_f(v0); v1 = silu_f(v1); v2 = silu_f(v2); v3 = silu_f(v3); }
            unsigned h01, l01, h23, l23;
            split2(make_float2(v0, v1), h01, l01);
            split2(make_float2(v2, v3), h23, l23);
            int w0 = (g + 16 * mt) * 36 + nt * 4 + c;
            int w1 = (g + 8 + 16 * mt) * 36 + nt * 4 + c;
            oh[w0] = h01; ol[w0] = l01;
            oh[w1] = h23; ol[w1] = l23;
        }
}

// ---------------- init ----------------
__global__ void init_kernel(const int* __restrict__ nt, const float* __restrict__ emb,
                            const float* __restrict__ pos) {
    int i = blockIdx.x * blockDim.x + threadIdx.x;
    int st = gridDim.x * blockDim.x;
    for (int j = i; j < NN * 32; j += st) {
        int node = j >> 5, w = j & 31;
        int t = nt[node];
        float2 v = *(const float2*)&emb[t * 64 + 2 * w];
        unsigned hw, lw;
        split2(v, hw, lw);
        g_hh[j] = hw; g_hl[j] = lw;
        *(float2*)&g_h[node * 64 + 2 * w] = v;
    }
    for (int j = i; j < NN * 3; j += st) g_pos[j] = pos[j];
    for (int j = i; j < NN; j += st) g_deg[j] = 0.0f;
}

__global__ void deg_kernel(const int* __restrict__ ei) {
    int i = blockIdx.x * blockDim.x + threadIdx.x;
    int st = gridDim.x * blockDim.x;
    for (int e = i; e < NE; e += st) atomicAdd(&g_deg[ei[NE + e]], 1.0f);
}

__global__ void zero_layer_kernel() {
    int i = blockIdx.x * blockDim.x + threadIdx.x;
    int st = gridDim.x * blockDim.x;
    for (int j = i; j < NN * HD; j += st) g_agg[j] = 0.0f;
    for (int j = i; j < NN * 3; j += st) g_pacc[j] = 0.0f;
}

// =====================================================================
// Edge kernel
// =====================================================================
#define EDGE_SMEM_B (76800 + 16 * 9216)   // 224256

__global__ __launch_bounds__(512) void edge_kernel(
    const int* __restrict__ ei, const float* __restrict__ ea,
    const float* __restrict__ ew1, const float* __restrict__ eb1,
    const float* __restrict__ ew2, const float* __restrict__ eb2,
    const float* __restrict__ cw1, const float* __restrict__ cb1,
    const float* __restrict__ cw2, const float* __restrict__ cb2,
    int layer) {
    extern __shared__ char smb[];
    __nv_bfloat16* w1h_e = (__nv_bfloat16*)(smb + 0);
    __nv_bfloat16* w1l_e = (__nv_bfloat16*)(smb + 19456);
    __nv_bfloat16* w2h_e = (__nv_bfloat16*)(smb + 38912);
    __nv_bfloat16* w2l_e = (__nv_bfloat16*)(smb + 48128);
    __nv_bfloat16* c1h_e = (__nv_bfloat16*)(smb + 57344);
    __nv_bfloat16* c1l_e = (__nv_bfloat16*)(smb + 66560);
    float* sB1 = (float*)(smb + 75776);
    float* sB2 = sB1 + 64;
    float* sCB1 = sB2 + 64;
    float* sC2 = sCB1 + 64;

    int tid = threadIdx.x;
    const float* w1g = ew1 + layer * MIN_D * HD;
    for (int i = tid; i < 64 * 152; i += blockDim.x) {
        int n = i / 152, k = i % 152;
        float v = (k < MIN_D) ? w1g[k * 64 + n] : 0.0f;
        split_store(v, w1h_e + n * 152 + k, w1l_e + n * 152 + k);
    }
    const float* w2g = ew2 + layer * 64 * 64;
    const float* c1g = cw1 + layer * 64 * 64;
    for (int i = tid; i < 64 * 72; i += blockDim.x) {
        int n = i / 72, k = i % 72;
        float v2 = (k < 64) ? w2g[k * 64 + n] : 0.0f;
        float vc = (k < 64) ? c1g[k * 64 + n] : 0.0f;
        split_store(v2, w2h_e + n * 72 + k, w2l_e + n * 72 + k);
        split_store(vc, c1h_e + n * 72 + k, c1l_e + n * 72 + k);
    }
    for (int i = tid; i < 64; i += blockDim.x) {
        sB1[i] = eb1[layer * 64 + i];
        sB2[i] = eb2[layer * 64 + i];
        sCB1[i] = cb1[layer * 64 + i];
        sC2[i] = cw2[layer * 64 + i];
    }
    __syncthreads();
    float cb2v = cb2[layer];

    int lane = tid & 31;
    int wl = tid >> 5;
    int g = lane >> 2;
    int c = lane & 3;
    unsigned* bhw = (unsigned*)(smb + 76800 + wl * 9216);
    unsigned* blw = bhw + 1152;
    __nv_bfloat16* bh_e = (__nv_bfloat16*)bhw;
    __nv_bfloat16* bl_e = (__nv_bfloat16*)blw;

    // per-lane ldmatrix base addresses
    unsigned sbase = smem_u32(bhw);
    unsigned aH = sbase + ((lane & 15) * 36) * 4 + (lane >> 4) * 16;
    unsigned aL = aH + 4608;
    int wr = lane & 7, whalf = (lane >> 3) & 1, wq = lane >> 4;
    unsigned w1H = smem_u32(w1h_e) + ((wq * 8 + wr) * 76) * 4 + whalf * 16;
    unsigned w1L = smem_u32(w1l_e) + ((wq * 8 + wr) * 76) * 4 + whalf * 16;
    unsigned w2H = smem_u32(w2h_e) + ((wq * 8 + wr) * 36) * 4 + whalf * 16;
    unsigned w2L = smem_u32(w2l_e) + ((wq * 8 + wr) * 36) * 4 + whalf * 16;
    unsigned c1H = smem_u32(c1h_e) + ((wq * 8 + wr) * 36) * 4 + whalf * 16;
    unsigned c1L = smem_u32(c1l_e) + ((wq * 8 + wr) * 36) * 4 + whalf * 16;

    int subrow = lane >> 3;    // 0..3
    int ck = lane & 7;         // 16B chunk within row

    int warp = (blockIdx.x * blockDim.x + tid) >> 5;
    int nwarp = (gridDim.x * blockDim.x) >> 5;

    // prefetch first tile's indices
    int cur_src = 0, cur_dst = 0;
    if (warp < NTILE_E) {
        cur_src = ei[warp * 32 + lane];
        cur_dst = ei[NE + warp * 32 + lane];
    }

    for (int tile = warp; tile < NTILE_E; tile += nwarp) {
        int e = tile * 32 + lane;
        int src = cur_src, dst = cur_dst;

        // ---- issue chunk0 (h[dst]) cp.asyncs ----
#pragma unroll
        for (int t4 = 0; t4 < 8; t4++) {
            int e2 = t4 * 4 + subrow;
            int row = __shfl_sync(0xffffffffu, dst, e2);
            unsigned d = sbase + (e2 * 36 + ck * 4) * 4;
            cp16(d, &g_hh[row * 32 + ck * 4]);
            cp16(d + 4608, &g_hl[row * 32 + ck * 4]);
        }
        cp_commit();

        // overlap: pos/ea loads + next-tile index prefetch
        float4 eav = *(const float4*)(ea + (size_t)e * 4);
        float rx = g_pos[dst * 3 + 0] - g_pos[src * 3 + 0];
        float ry = g_pos[dst * 3 + 1] - g_pos[src * 3 + 1];
        float rz = g_pos[dst * 3 + 2] - g_pos[src * 3 + 2];
        float d2 = rx * rx + ry * ry + rz * rz;
        int tn = tile + nwarp;
        if (tn < NTILE_E) {
            cur_src = ei[tn * 32 + lane];
            cur_dst = ei[NE + tn * 32 + lane];
        }

        float acc[16][4];
#pragma unroll
        for (int mt = 0; mt < 2; mt++)
#pragma unroll
            for (int nt = 0; nt < 8; nt++) {
                float b0 = sB1[nt * 8 + 2 * c], b1 = sB1[nt * 8 + 2 * c + 1];
                acc[mt * 8 + nt][0] = b0; acc[mt * 8 + nt][1] = b1;
                acc[mt * 8 + nt][2] = b0; acc[mt * 8 + nt][3] = b1;
            }

        cp_wait();
        __syncwarp();
#pragma unroll
        for (int kt = 0; kt < 4; kt++)
            gemm_kt_lm(acc, aH, aL, w1H, w1L, 4864, kt, kt);
        __syncwarp();

        // ---- chunk1 (h[src]) ----
#pragma unroll
        for (int t4 = 0; t4 < 8; t4++) {
            int e2 = t4 * 4 + subrow;
            int row = __shfl_sync(0xffffffffu, src, e2);
            unsigned d = sbase + (e2 * 36 + ck * 4) * 4;
            cp16(d, &g_hh[row * 32 + ck * 4]);
            cp16(d + 4608, &g_hl[row * 32 + ck * 4]);
        }
        cp_commit();
        cp_wait();
        __syncwarp();
#pragma unroll
        for (int kt = 0; kt < 4; kt++)
            gemm_kt_lm(acc, aH, aL, w1H, w1L, 4864, kt, 4 + kt);
        __syncwarp();

        // ---- tail chunk (features 128..143: d2, ea, zeros) ----
        {
            float tf[16];
            tf[0] = d2; tf[1] = eav.x; tf[2] = eav.y; tf[3] = eav.z; tf[4] = eav.w;
#pragma unroll
            for (int t = 5; t < 16; t++) tf[t] = 0.0f;
#pragma unroll
            for (int t = 0; t < 8; t++) {
                unsigned hw, lw2;
                split2(make_float2(tf[2 * t], tf[2 * t + 1]), hw, lw2);
                bhw[lane * 36 + t] = hw;
                blw[lane * 36 + t] = lw2;
            }
        }
        __syncwarp();
        gemm_kt_lm(acc, aH, aL, w1H, w1L, 4864, 0, 8);
        __syncwarp();

        // ---- m1 = silu; stage; GEMM2 ----
        act_store(acc, bhw, blw, g, c, true);
        __syncwarp();

        float acc2[16][4];
#pragma unroll
        for (int mt = 0; mt < 2; mt++)
#pragma unroll
            for (int nt = 0; nt < 8; nt++) {
                float b0 = sB2[nt * 8 + 2 * c], b1 = sB2[nt * 8 + 2 * c + 1];
                acc2[mt * 8 + nt][0] = b0; acc2[mt * 8 + nt][1] = b1;
                acc2[mt * 8 + nt][2] = b0; acc2[mt * 8 + nt][3] = b1;
            }
#pragma unroll
        for (int kt = 0; kt < 4; kt++)
            gemm_kt_lm(acc2, aH, aL, w2H, w2L, 2304, kt, kt);
        __syncwarp();

        // ---- m = silu; stage; coord GEMM ----
        act_store(acc2, bhw, blw, g, c, true);
        __syncwarp();

        float acc3[16][4];
#pragma unroll
        for (int mt = 0; mt < 2; mt++)
#pragma unroll
            for (int nt = 0; nt < 8; nt++) {
                float b0 = sCB1[nt * 8 + 2 * c], b1 = sCB1[nt * 8 + 2 * c + 1];
                acc3[mt * 8 + nt][0] = b0; acc3[mt * 8 + nt][1] = b1;
                acc3[mt * 8 + nt][2] = b0; acc3[mt * 8 + nt][3] = b1;
            }
#pragma unroll
        for (int kt = 0; kt < 4; kt++)
            gemm_kt_lm(acc3, aH, aL, c1H, c1L, 2304, kt, kt);

        // coord scalar
        float p0 = 0.f, p1 = 0.f, p2 = 0.f, p3 = 0.f;
#pragma unroll
        for (int nt = 0; nt < 8; nt++) {
            float w0 = sC2[nt * 8 + 2 * c], w1 = sC2[nt * 8 + 2 * c + 1];
            p0 += silu_f(acc3[nt][0]) * w0 + silu_f(acc3[nt][1]) * w1;
            p1 += silu_f(acc3[nt][2]) * w0 + silu_f(acc3[nt][3]) * w1;
            p2 += silu_f(acc3[8 + nt][0]) * w0 + silu_f(acc3[8 + nt][1]) * w1;
            p3 += silu_f(acc3[8 + nt][2]) * w0 + silu_f(acc3[8 + nt][3]) * w1;
        }
        p0 += __shfl_xor_sync(0xffffffffu, p0, 1); p0 += __shfl_xor_sync(0xffffffffu, p0, 2);
        p1 += __shfl_xor_sync(0xffffffffu, p1, 1); p1 += __shfl_xor_sync(0xffffffffu, p1, 2);
        p2 += __shfl_xor_sync(0xffffffffu, p2, 1); p2 += __shfl_xor_sync(0xffffffffu, p2, 2);
        p3 += __shfl_xor_sync(0xffffffffu, p3, 1); p3 += __shfl_xor_sync(0xffffffffu, p3, 2);
        int srcl = (lane & 7) * 4;
        float t0 = __shfl_sync(0xffffffffu, p0, srcl);
        float t1 = __shfl_sync(0xffffffffu, p1, srcl);
        float t2 = __shfl_sync(0xffffffffu, p2, srcl);
        float t3 = __shfl_sync(0xffffffffu, p3, srcl);
        int q = lane >> 3;
        float cc = (q == 0) ? t0 : ((q == 1) ? t1 : ((q == 2) ? t2 : t3));
        cc += cb2v;

        atomicAdd(&g_pacc[dst * 3 + 0], rx * cc);
        atomicAdd(&g_pacc[dst * 3 + 1], ry * cc);
        atomicAdd(&g_pacc[dst * 3 + 2], rz * cc);

        // message scatter (m = hi + lo from staging) — coalesced atomics
#pragma unroll 4
        for (int e2 = 0; e2 < 32; e2++) {
            int drow = __shfl_sync(0xffffffffu, dst, e2);
            float v0 = __bfloat162float(bh_e[e2 * 72 + lane]) + __bfloat162float(bl_e[e2 * 72 + lane]);
            float v1 = __bfloat162float(bh_e[e2 * 72 + 32 + lane]) + __bfloat162float(bl_e[e2 * 72 + 32 + lane]);
            atomicAdd(&g_agg[drow * 64 + lane], v0);
            atomicAdd(&g_agg[drow * 64 + 32 + lane], v1);
        }
        __syncwarp();
    }
}

// =====================================================================
// Node kernel
// =====================================================================
#define NODE_SMEM_B (53760 + 16 * 9216)   // 201216

__global__ __launch_bounds__(512) void node_kernel(
    const float* __restrict__ nw1, const float* __restrict__ nb1,
    const float* __restrict__ nw2, const float* __restrict__ nb2,
    int layer) {
    extern __shared__ char smb[];
    __nv_bfloat16* w1h_e = (__nv_bfloat16*)(smb + 0);
    __nv_bfloat16* w1l_e = (__nv_bfloat16*)(smb + 17408);
    __nv_bfloat16* w2h_e = (__nv_bfloat16*)(smb + 34816);
    __nv_bfloat16* w2l_e = (__nv_bfloat16*)(smb + 44032);
    float* sB1 = (float*)(smb + 53248);
    float* sB2 = sB1 + 64;

    int tid = threadIdx.x;
    const float* w1g = nw1 + layer * 128 * 64;
    for (int i = tid; i < 64 * 136; i += blockDim.x) {
        int n = i / 136, k = i % 136;
        float v = (k < 128) ? w1g[k * 64 + n] : 0.0f;
        split_store(v, w1h_e + n * 136 + k, w1l_e + n * 136 + k);
    }
    const float* w2g = nw2 + layer * 64 * 64;
    for (int i = tid; i < 64 * 72; i += blockDim.x) {
        int n = i / 72, k = i % 72;
        float v = (k < 64) ? w2g[k * 64 + n] : 0.0f;
        split_store(v, w2h_e + n * 72 + k, w2l_e + n * 72 + k);
    }
    for (int i = tid; i < 64; i += blockDim.x) {
        sB1[i] = nb1[layer * 64 + i];
        sB2[i] = nb2[layer * 64 + i];
    }
    __syncthreads();

    int lane = tid & 31;
    int wl = tid >> 5;
    int g = lane >> 2;
    int c = lane & 3;
    unsigned* bhw = (unsigned*)(smb + 53760 + wl * 9216);
    unsigned* blw = bhw + 1152;

    unsigned sbase = smem_u32(bhw);
    unsigned aH = sbase + ((lane & 15) * 36) * 4 + (lane >> 4) * 16;
    unsigned aL = aH + 4608;
    int wr = lane & 7, whalf = (lane >> 3) & 1, wq = lane >> 4;
    unsigned w1H = smem_u32(w1h_e) + ((wq * 8 + wr) * 68) * 4 + whalf * 16;
    unsigned w1L = smem_u32(w1l_e) + ((wq * 8 + wr) * 68) * 4 + whalf * 16;
    unsigned w2H = smem_u32(w2h_e) + ((wq * 8 + wr) * 36) * 4 + whalf * 16;
    unsigned w2L = smem_u32(w2l_e) + ((wq * 8 + wr) * 36) * 4 + whalf * 16;

    int subrow = lane >> 3;
    int ck = lane & 7;

    int warp = (blockIdx.x * blockDim.x + tid) >> 5;
    int nwarp = (gridDim.x * blockDim.x) >> 5;

    for (int tile = warp; tile < NTILE_N; tile += nwarp) {
        int base = tile * 32;
        int n = base + lane;

        // chunk0: h via cp.async
#pragma unroll
        for (int t4 = 0; t4 < 8; t4++) {
            int e2 = t4 * 4 + subrow;
            int row = base + e2; if (row >= NN) row = NN - 1;
            unsigned d = sbase + (e2 * 36 + ck * 4) * 4;
            cp16(d, &g_hh[row * 32 + ck * 4]);
            cp16(d + 4608, &g_hl[row * 32 + ck * 4]);
        }
        cp_commit();

        if (n < NN) {
            float d = g_deg[n];
            if (d < 1.0f) d = 1.0f;
            float inv = 1.0f / d;
            g_pos[n * 3 + 0] += g_pacc[n * 3 + 0] * inv;
            g_pos[n * 3 + 1] += g_pacc[n * 3 + 1] * inv;
            g_pos[n * 3 + 2] += g_pacc[n * 3 + 2] * inv;
        }

        float acc[16][4];
#pragma unroll
        for (int mt = 0; mt < 2; mt++)
#pragma unroll
            for (int nt = 0; nt < 8; nt++) {
                float b0 = sB1[nt * 8 + 2 * c], b1 = sB1[nt * 8 + 2 * c + 1];
                acc[mt * 8 + nt][0] = b0; acc[mt * 8 + nt][1] = b1;
                acc[mt * 8 + nt][2] = b0; acc[mt * 8 + nt][3] = b1;
            }

        cp_wait();
        __syncwarp();
#pragma unroll
        for (int kt = 0; kt < 4; kt++)
            gemm_kt_lm(acc, aH, aL, w1H, w1L, 4352, kt, kt);
        __syncwarp();

        // chunk1: agg (fp32 -> split -> STS)
#pragma unroll 4
        for (int e2 = 0; e2 < 32; e2++) {
            int row = base + e2; if (row >= NN) row = NN - 1;
            float2 v = *(const float2*)&g_agg[row * 64 + 2 * lane];
            unsigned hw, lw2;
            split2(v, hw, lw2);
            bhw[e2 * 36 + lane] = hw;
            blw[e2 * 36 + lane] = lw2;
        }
        __syncwarp();
#pragma unroll
        for (int kt = 0; kt < 4; kt++)
            gemm_kt_lm(acc, aH, aL, w1H, w1L, 4352, kt, 4 + kt);
        __syncwarp();

        // m1 = silu; stage; GEMM2
        act_store(acc, bhw, blw, g, c, true);
        __syncwarp();

        float acc2[16][4];
#pragma unroll
        for (int mt = 0; mt < 2; mt++)
#pragma unroll
            for (int nt = 0; nt < 8; nt++) {
                float b0 = sB2[nt * 8 + 2 * c], b1 = sB2[nt * 8 + 2 * c + 1];
                acc2[mt * 8 + nt][0] = b0; acc2[mt * 8 + nt][1] = b1;
                acc2[mt * 8 + nt][2] = b0; acc2[mt * 8 + nt][3] = b1;
            }
#pragma unroll
        for (int kt = 0; kt < 4; kt++)
            gemm_kt_lm(acc2, aH, aL, w2H, w2L, 2304, kt, kt);

        // residual h += out; also refresh split copies
#pragma unroll
        for (int mt = 0; mt < 2; mt++)
#pragma unroll
            for (int nt = 0; nt < 8; nt++) {
                int r0 = base + g + 16 * mt;
                int r1 = r0 + 8;
                int col = nt * 8 + 2 * c;
                if (r0 < NN) {
                    float2* p = (float2*)&g_h[r0 * 64 + col];
                    float2 o = *p;
                    o.x += acc2[mt * 8 + nt][0]; o.y += acc2[mt * 8 + nt][1];
                    *p = o;
                    unsigned hw, lw2;
                    split2(o, hw, lw2);
                    g_hh[r0 * 32 + nt * 4 + c] = hw;
                    g_hl[r0 * 32 + nt * 4 + c] = lw2;
                }
                if (r1 < NN) {
                    float2* p = (float2*)&g_h[r1 * 64 + col];
                    float2 o = *p;
                    o.x += acc2[mt * 8 + nt][2]; o.y += acc2[mt * 8 + nt][3];
                    *p = o;
                    unsigned hw, lw2;
                    split2(o, hw, lw2);
                    g_hh[r1 * 32 + nt * 4 + c] = hw;
                    g_hl[r1 * 32 + nt * 4 + c] = lw2;
                }
            }
        __syncwarp();
    }
}

// ---------------- pooling ----------------
__global__ void pool_zero_kernel() {
    int i = blockIdx.x * blockDim.x + threadIdx.x;
    int st = gridDim.x * blockDim.x;
    for (int j = i; j < NG * HD; j += st) g_gsum[j] = 0.0f;
    for (int j = i; j < NG; j += st) g_gcnt[j] = 0.0f;
}

__global__ void pool_kernel(const int* __restrict__ batch) {
    int tid = threadIdx.x;
    int lane = tid & 31;
    int warp = (blockIdx.x * blockDim.x + tid) >> 5;
    int nwarp = (gridDim.x * blockDim.x) >> 5;
    for (int n = warp; n < NN; n += nwarp) {
        int b = batch[n];
        atomicAdd(&g_gsum[b * HD + lane], g_h[n * HD + lane]);
        atomicAdd(&g_gsum[b * HD + 32 + lane], g_h[n * HD + 32 + lane]);
        if (lane == 0) atomicAdd(&g_gcnt[b], 1.0f);
    }
}

// ---------------- per-graph: pre-MLP, 4-qubit circuit, post-MLP ----------------
__global__ void final_kernel(const float* __restrict__ prew, const float* __restrict__ preb,
                             const float* __restrict__ qw,
                             const float* __restrict__ pw1, const float* __restrict__ pb1,
                             const float* __restrict__ pw2, const float* __restrict__ pb2,
                             float* __restrict__ out) {
    int g = threadIdx.x;
    if (g >= NG) return;
    float cnt = g_gcnt[g];
    if (cnt < 1.0f) cnt = 1.0f;
    float qin[4];
    for (int q = 0; q < 4; q++) qin[q] = preb[q];
    for (int k = 0; k < HD; k++) {
        float gv = g_gsum[g * HD + k] / cnt;
        for (int q = 0; q < 4; q++) qin[q] += gv * prew[k * 4 + q];
    }

    float pr[16], pi[16];
    for (int i = 0; i < 16; i++) { pr[i] = 0.0f; pi[i] = 0.0f; }
    pr[0] = 1.0f;

    for (int q = 0; q < 4; q++) {
        int s = 8 >> q;
        float ch = cosf(qin[q] * 0.5f);
        float sh = sinf(qin[q] * 0.5f);
        for (int i = 0; i < 16; i++) {
            if (i & s) continue;
            int j = i | s;
            float ar = pr[i], ai = pi[i], br = pr[j], bi = pi[j];
            pr[i] = ch * ar + sh * bi;  pi[i] = ch * ai - sh * br;
            pr[j] = ch * br + sh * ai;  pi[j] = ch * bi - sh * ar;
        }
    }
    for (int l = 0; l < 2; l++) {
        for (int q = 0; q < 4; q++) {
            int s = 8 >> q;
            float ch = cosf(qw[l * 4 + q] * 0.5f);
            float sh = sinf(qw[l * 4 + q] * 0.5f);
            for (int i = 0; i < 16; i++) {
                if (i & s) continue;
                int j = i | s;
                float ar = pr[i], ai = pi[i], br = pr[j], bi = pi[j];
                pr[i] = ch * ar - sh * br;  pi[i] = ch * ai - sh * bi;
                pr[j] = sh * ar + ch * br;  pi[j] = sh * ai + ch * bi;
            }
        }
        for (int q = 0; q < 4; q++) {
            int cs = 8 >> q;
            int ts = 8 >> ((q + 1) & 3);
            for (int i = 0; i < 16; i++) {
                if ((i & cs) && !(i & ts)) {
                    int j = i | ts;
                    float t;
                    t = pr[i]; pr[i] = pr[j]; pr[j] = t;
                    t = pi[i]; pi[i] = pi[j]; pi[j] = t;
                }
            }
        }
    }
    float qo[4] = {0.0f, 0.0f, 0.0f, 0.0f};
    for (int i = 0; i < 16; i++) {
        float p = pr[i] * pr[i] + pi[i] * pi[i];
        for (int q = 0; q < 4; q++) qo[q] += (i & (8 >> q)) ? -p : p;
    }

    float acc = pb2[0];
    for (int j = 0; j < HD; j++) {
        float t = pb1[j];
        for (int q = 0; q < 4; q++) t += qo[q] * pw1[q * HD + j];
        acc += silu_f(t) * pw2[j];
    }
    out[g] = acc;
}

// ---------------- launch ----------------
extern "C" void kernel_launch(void* const* d_in, const int* in_sizes, int n_in,
                              void* d_out, int out_size) {
    const int* nt = (const int*)d_in[0];
    const float* pos = (const float*)d_in[1];
    const int* ei = (const int*)d_in[2];
    const float* ea = (const float*)d_in[3];
    const int* batch = (const int*)d_in[4];
    const float* emb = (const float*)d_in[5];
    const float* ew1 = (const float*)d_in[6];
    const float* eb1 = (const float*)d_in[7];
    const float* ew2 = (const float*)d_in[8];
    const float* eb2 = (const float*)d_in[9];
    const float* cw1 = (const float*)d_in[10];
    const float* cb1 = (const float*)d_in[11];
    const float* cw2 = (const float*)d_in[12];
    const float* cb2 = (const float*)d_in[13];
    const float* nw1 = (const float*)d_in[14];
    const float* nb1 = (const float*)d_in[15];
    const float* nw2 = (const float*)d_in[16];
    const float* nb2 = (const float*)d_in[17];
    const float* prew = (const float*)d_in[18];
    const float* preb = (const float*)d_in[19];
    const float* qw = (const float*)d_in[20];
    const float* pw1 = (const float*)d_in[21];
    const float* pb1 = (const float*)d_in[22];
    const float* pw2 = (const float*)d_in[23];
    const float* pb2 = (const float*)d_in[24];
    float* out = (float*)d_out;

    cudaFuncSetAttribute(edge_kernel, cudaFuncAttributeMaxDynamicSharedMemorySize, EDGE_SMEM_B);
    cudaFuncSetAttribute(node_kernel, cudaFuncAttributeMaxDynamicSharedMemorySize, NODE_SMEM_B);

    init_kernel<<<512, 256>>>(nt, emb, pos);
    deg_kernel<<<512, 256>>>(ei);
    for (int l = 0; l < NL; l++) {
        zero_layer_kernel<<<512, 256>>>();
        edge_kernel<<<148, 512, EDGE_SMEM_B>>>(ei, ea, ew1, eb1, ew2, eb2,
                                               cw1, cb1, cw2, cb2, l);
        node_kernel<<<148, 512, NODE_SMEM_B>>>(nw1, nb1, nw2, nb2, l);
    }
    pool_zero_kernel<<<64, 256>>>();
    pool_kernel<<<512, 256>>>(batch);
    final_kernel<<<1, 128>>>(prew, preb, qw, pw1, pb1, pw2, pb2, out);
}

// round 12
// speedup vs baseline: 5.1266x; 1.1725x over previous
#include <cuda_runtime.h>
#include <cuda_bf16.h>
#include <math.h>

#define NN 50000
#define NE 800000
#define HD 64
#define NG 128
#define NL 3
#define MIN_D 133
#define NTILE_E16 (NE / 16)        // 50000
#define NTILE_N ((NN + 31) / 32)   // 1563

// ---------------- scratch ----------------
__device__ float g_h[NN * HD];
__device__ unsigned g_hh[NN * 32];   // h hi, packed bf16x2 per word
__device__ unsigned g_hl[NN * 32];   // h lo
__device__ float g_pos[NN * 3];
__device__ float g_agg[NN * HD];
__device__ float g_pacc[NN * 3];
__device__ float g_deg[NN];
__device__ float g_gsum[NG * HD];
__device__ float g_gcnt[NG];

__device__ __forceinline__ float silu_f(float x) { return x / (1.0f + __expf(-x)); }

__device__ __forceinline__ void mma16816(float d[4], const unsigned* a, const unsigned* b) {
    asm volatile(
        "mma.sync.aligned.m16n8k16.row.col.f32.bf16.bf16.f32 "
        "{%0,%1,%2,%3},{%4,%5,%6,%7},{%8,%9},{%0,%1,%2,%3};\n"
        : "+f"(d[0]), "+f"(d[1]), "+f"(d[2]), "+f"(d[3])
        : "r"(a[0]), "r"(a[1]), "r"(a[2]), "r"(a[3]), "r"(b[0]), "r"(b[1]));
}

__device__ __forceinline__ void ldm4(unsigned* r, unsigned addr) {
    asm volatile("ldmatrix.sync.aligned.m8n8.x4.shared.b16 {%0,%1,%2,%3}, [%4];\n"
        : "=r"(r[0]), "=r"(r[1]), "=r"(r[2]), "=r"(r[3]) : "r"(addr));
}

__device__ __forceinline__ unsigned smem_u32(const void* p) {
    return (unsigned)__cvta_generic_to_shared(p);
}

__device__ __forceinline__ void cp16(unsigned dst, const void* src) {
    asm volatile("cp.async.cg.shared.global [%0], [%1], 16;\n" :: "r"(dst), "l"(src));
}
__device__ __forceinline__ void cp_commit() {
    asm volatile("cp.async.commit_group;\n" ::: "memory");
}
__device__ __forceinline__ void cp_wait() {
    asm volatile("cp.async.wait_all;\n" ::: "memory");
}

__device__ __forceinline__ void split_store(float v, __nv_bfloat16* ph, __nv_bfloat16* pl) {
    __nv_bfloat16 h = __float2bfloat16(v);
    *ph = h;
    *pl = __float2bfloat16(v - __bfloat162float(h));
}

__device__ __forceinline__ void split2(float2 v, unsigned& hw, unsigned& lw) {
    __nv_bfloat162 h2, l2;
    h2.x = __float2bfloat16(v.x); l2.x = __float2bfloat16(v.x - __bfloat162float(h2.x));
    h2.y = __float2bfloat16(v.y); l2.y = __float2bfloat16(v.y - __bfloat162float(h2.y));
    hw = *(unsigned*)&h2;
    lw = *(unsigned*)&l2;
}

// M=16 k-tile: acc[8][4]; A 16x16 via two ldmatrix.x4 (hi+lo); 8 n8-tiles of W.
__device__ __forceinline__ void gemm16(float (*acc)[4],
        unsigned aAddrH, unsigned aAddrL, unsigned wH, unsigned wL,
        int wgb, int ktW) {
    unsigned ah[4], al[4];
    ldm4(ah, aAddrH);
    ldm4(al, aAddrL);
#pragma unroll
    for (int grp = 0; grp < 4; grp++) {
        unsigned bh[4], bl[4];
        ldm4(bh, wH + grp * wgb + ktW * 32);
        ldm4(bl, wL + grp * wgb + ktW * 32);
        mma16816(acc[2 * grp],     ah, bh);     mma16816(acc[2 * grp],     ah, bl);     mma16816(acc[2 * grp],     al, bh);
        mma16816(acc[2 * grp + 1], ah, bh + 2); mma16816(acc[2 * grp + 1], ah, bl + 2); mma16816(acc[2 * grp + 1], al, bh + 2);
    }
}

// hi/lo split + store 8 fragments to staging (36-word rows); values already activated
__device__ __forceinline__ void store_frags16(float (*acc)[4], unsigned* oh, unsigned* ol,
                                              int g, int c) {
#pragma unroll
    for (int nt = 0; nt < 8; nt++) {
        unsigned h01, l01, h23, l23;
        split2(make_float2(acc[nt][0], acc[nt][1]), h01, l01);
        split2(make_float2(acc[nt][2], acc[nt][3]), h23, l23);
        int w0 = g * 36 + nt * 4 + c;
        int w1 = (g + 8) * 36 + nt * 4 + c;
        oh[w0] = h01; ol[w0] = l01;
        oh[w1] = h23; ol[w1] = l23;
    }
}

// ---------------- init ----------------
__global__ void init_kernel(const int* __restrict__ nt, const float* __restrict__ emb,
                            const float* __restrict__ pos) {
    int i = blockIdx.x * blockDim.x + threadIdx.x;
    int st = gridDim.x * blockDim.x;
    for (int j = i; j < NN * 32; j += st) {
        int node = j >> 5, w = j & 31;
        int t = nt[node];
        float2 v = *(const float2*)&emb[t * 64 + 2 * w];
        unsigned hw, lw;
        split2(v, hw, lw);
        g_hh[j] = hw; g_hl[j] = lw;
        *(float2*)&g_h[node * 64 + 2 * w] = v;
    }
    for (int j = i; j < NN * 3; j += st) g_pos[j] = pos[j];
    for (int j = i; j < NN; j += st) g_deg[j] = 0.0f;
}

__global__ void deg_kernel(const int* __restrict__ ei) {
    int i = blockIdx.x * blockDim.x + threadIdx.x;
    int st = gridDim.x * blockDim.x;
    for (int e = i; e < NE; e += st) atomicAdd(&g_deg[ei[NE + e]], 1.0f);
}

__global__ void zero_layer_kernel() {
    int i = blockIdx.x * blockDim.x + threadIdx.x;
    int st = gridDim.x * blockDim.x;
    for (int j = i; j < NN * HD; j += st) g_agg[j] = 0.0f;
    for (int j = i; j < NN * 3; j += st) g_pacc[j] = 0.0f;
}

// =====================================================================
// Edge kernel: 16 edges/warp, 768 threads (24 warps), pipelined gathers.
// smem: [0,76800) weights+biases (as R10); then per-warp 5632B:
//   [A-hi 2304][A-lo 2304][tail-hi 512][tail-lo 512]
// =====================================================================
#define EDGE_SMEM_B (76800 + 24 * 5632)   // 211968

__global__ __launch_bounds__(768) void edge_kernel(
    const int* __restrict__ ei, const float* __restrict__ ea,
    const float* __restrict__ ew1, const float* __restrict__ eb1,
    const float* __restrict__ ew2, const float* __restrict__ eb2,
    const float* __restrict__ cw1, const float* __restrict__ cb1,
    const float* __restrict__ cw2, const float* __restrict__ cb2,
    int layer) {
    extern __shared__ char smb[];
    __nv_bfloat16* w1h_e = (__nv_bfloat16*)(smb + 0);
    __nv_bfloat16* w1l_e = (__nv_bfloat16*)(smb + 19456);
    __nv_bfloat16* w2h_e = (__nv_bfloat16*)(smb + 38912);
    __nv_bfloat16* w2l_e = (__nv_bfloat16*)(smb + 48128);
    __nv_bfloat16* c1h_e = (__nv_bfloat16*)(smb + 57344);
    __nv_bfloat16* c1l_e = (__nv_bfloat16*)(smb + 66560);
    float* sB1 = (float*)(smb + 75776);
    float* sB2 = sB1 + 64;
    float* sCB1 = sB2 + 64;
    float* sC2 = sCB1 + 64;

    int tid = threadIdx.x;
    const float* w1g = ew1 + layer * MIN_D * HD;
    for (int i = tid; i < 64 * 152; i += blockDim.x) {
        int n = i / 152, k = i % 152;
        float v = (k < MIN_D) ? w1g[k * 64 + n] : 0.0f;
        split_store(v, w1h_e + n * 152 + k, w1l_e + n * 152 + k);
    }
    const float* w2g = ew2 + layer * 64 * 64;
    const float* c1g = cw1 + layer * 64 * 64;
    for (int i = tid; i < 64 * 72; i += blockDim.x) {
        int n = i / 72, k = i % 72;
        float v2 = (k < 64) ? w2g[k * 64 + n] : 0.0f;
        float vc = (k < 64) ? c1g[k * 64 + n] : 0.0f;
        split_store(v2, w2h_e + n * 72 + k, w2l_e + n * 72 + k);
        split_store(vc, c1h_e + n * 72 + k, c1l_e + n * 72 + k);
    }
    for (int i = tid; i < 64; i += blockDim.x) {
        sB1[i] = eb1[layer * 64 + i];
        sB2[i] = eb2[layer * 64 + i];
        sCB1[i] = cb1[layer * 64 + i];
        sC2[i] = cw2[layer * 64 + i];
    }
    __syncthreads();
    float cb2v = cb2[layer];

    int lane = tid & 31;
    int wl = tid >> 5;
    int g = lane >> 2;
    int c = lane & 3;
    unsigned* bhw = (unsigned*)(smb + 76800 + wl * 5632);
    unsigned* blw = bhw + 576;
    unsigned* thw = bhw + 1152;
    unsigned* tlw = thw + 128;

    unsigned sbase = smem_u32(bhw);
    unsigned aH = sbase + (lane & 15) * 144 + (lane >> 4) * 16;
    unsigned aL = aH + 2304;
    unsigned tbase = smem_u32(thw);
    unsigned tH = tbase + (lane & 15) * 32 + (lane >> 4) * 16;
    unsigned tL = tH + 512;
    int wr = lane & 7, whalf = (lane >> 3) & 1, wq = lane >> 4;
    unsigned w1H = smem_u32(w1h_e) + ((wq * 8 + wr) * 76) * 4 + whalf * 16;
    unsigned w1L = smem_u32(w1l_e) + ((wq * 8 + wr) * 76) * 4 + whalf * 16;
    unsigned w2H = smem_u32(w2h_e) + ((wq * 8 + wr) * 36) * 4 + whalf * 16;
    unsigned w2L = smem_u32(w2l_e) + ((wq * 8 + wr) * 36) * 4 + whalf * 16;
    unsigned c1H = smem_u32(c1h_e) + ((wq * 8 + wr) * 36) * 4 + whalf * 16;
    unsigned c1L = smem_u32(c1l_e) + ((wq * 8 + wr) * 36) * 4 + whalf * 16;

    int subrow = lane >> 3;    // 0..3
    int ck = lane & 7;         // 16B chunk within 128B row

    int warp = (blockIdx.x * blockDim.x + tid) >> 5;
    int nwarp = (gridDim.x * blockDim.x) >> 5;
    int el = lane & 15;        // edge slot within tile

    int src = 0, dst = 0;
    if (warp < NTILE_E16) {
        src = ei[warp * 16 + el];
        dst = ei[NE + warp * 16 + el];
        // issue chunk0 (h[dst]) for first tile
#pragma unroll
        for (int t4 = 0; t4 < 4; t4++) {
            int e2 = t4 * 4 + subrow;
            int row = __shfl_sync(0xffffffffu, dst, e2);
            unsigned d = sbase + (e2 * 36 + ck * 4) * 4;
            cp16(d, &g_hh[row * 32 + ck * 4]);
            cp16(d + 2304, &g_hl[row * 32 + ck * 4]);
        }
        cp_commit();
    }

    for (int tile = warp; tile < NTILE_E16; tile += nwarp) {
        int e = tile * 16 + el;
        float4 eav = *(const float4*)(ea + (size_t)e * 4);
        float rx = g_pos[dst * 3 + 0] - g_pos[src * 3 + 0];
        float ry = g_pos[dst * 3 + 1] - g_pos[src * 3 + 1];
        float rz = g_pos[dst * 3 + 2] - g_pos[src * 3 + 2];
        float d2 = rx * rx + ry * ry + rz * rz;

        int tn = tile + nwarp;
        int nsrc = src, ndst = dst;
        if (tn < NTILE_E16) {
            nsrc = ei[tn * 16 + el];
            ndst = ei[NE + tn * 16 + el];
        }

        float acc[8][4];
#pragma unroll
        for (int nt = 0; nt < 8; nt++) {
            float b0 = sB1[nt * 8 + 2 * c], b1 = sB1[nt * 8 + 2 * c + 1];
            acc[nt][0] = b0; acc[nt][1] = b1;
            acc[nt][2] = b0; acc[nt][3] = b1;
        }

        // ---- wait chunk0; GEMM1 features 0..63 (h[dst]) ----
        cp_wait();
        __syncwarp();
#pragma unroll
        for (int kt = 0; kt < 4; kt++)
            gemm16(acc, aH + kt * 32, aL + kt * 32, w1H, w1L, 4864, kt);
        __syncwarp();

        // ---- issue chunk1 (h[src]); overlap with tail stage + tail GEMM ----
#pragma unroll
        for (int t4 = 0; t4 < 4; t4++) {
            int e2 = t4 * 4 + subrow;
            int row = __shfl_sync(0xffffffffu, src, e2);
            unsigned d = sbase + (e2 * 36 + ck * 4) * 4;
            cp16(d, &g_hh[row * 32 + ck * 4]);
            cp16(d + 2304, &g_hl[row * 32 + ck * 4]);
        }
        cp_commit();

        if (lane < 16) {
            float tf[16];
            tf[0] = d2; tf[1] = eav.x; tf[2] = eav.y; tf[3] = eav.z; tf[4] = eav.w;
#pragma unroll
            for (int t = 5; t < 16; t++) tf[t] = 0.0f;
#pragma unroll
            for (int t = 0; t < 8; t++) {
                unsigned hw, lw2;
                split2(make_float2(tf[2 * t], tf[2 * t + 1]), hw, lw2);
                thw[lane * 8 + t] = hw;
                tlw[lane * 8 + t] = lw2;
            }
        }
        __syncwarp();
        gemm16(acc, tH, tL, w1H, w1L, 4864, 8);   // tail features 128..143

        cp_wait();
        __syncwarp();
#pragma unroll
        for (int kt = 0; kt < 4; kt++)
            gemm16(acc, aH + kt * 32, aL + kt * 32, w1H, w1L, 4864, 4 + kt);
        __syncwarp();

        // ---- m1 = silu(acc); stage; GEMM2 ----
#pragma unroll
        for (int nt = 0; nt < 8; nt++) {
            acc[nt][0] = silu_f(acc[nt][0]); acc[nt][1] = silu_f(acc[nt][1]);
            acc[nt][2] = silu_f(acc[nt][2]); acc[nt][3] = silu_f(acc[nt][3]);
        }
        store_frags16(acc, bhw, blw, g, c);
        __syncwarp();

        float acc2[8][4];
#pragma unroll
        for (int nt = 0; nt < 8; nt++) {
            float b0 = sB2[nt * 8 + 2 * c], b1 = sB2[nt * 8 + 2 * c + 1];
            acc2[nt][0] = b0; acc2[nt][1] = b1;
            acc2[nt][2] = b0; acc2[nt][3] = b1;
        }
#pragma unroll
        for (int kt = 0; kt < 4; kt++)
            gemm16(acc2, aH + kt * 32, aL + kt * 32, w2H, w2L, 2304, kt);
        __syncwarp();

        // ---- m = silu(acc2); stage; scatter from registers; GEMM3 ----
#pragma unroll
        for (int nt = 0; nt < 8; nt++) {
            acc2[nt][0] = silu_f(acc2[nt][0]); acc2[nt][1] = silu_f(acc2[nt][1]);
            acc2[nt][2] = silu_f(acc2[nt][2]); acc2[nt][3] = silu_f(acc2[nt][3]);
        }
        store_frags16(acc2, bhw, blw, g, c);
        __syncwarp();

        {
            int drow0 = __shfl_sync(0xffffffffu, dst, g);
            int drow1 = __shfl_sync(0xffffffffu, dst, g + 8);
            float* p0b = &g_agg[drow0 * 64 + 2 * c];
            float* p1b = &g_agg[drow1 * 64 + 2 * c];
#pragma unroll
            for (int nt = 0; nt < 8; nt++) {
                atomicAdd(p0b + nt * 8,     acc2[nt][0]);
                atomicAdd(p0b + nt * 8 + 1, acc2[nt][1]);
                atomicAdd(p1b + nt * 8,     acc2[nt][2]);
                atomicAdd(p1b + nt * 8 + 1, acc2[nt][3]);
            }
        }

        float acc3[8][4];
#pragma unroll
        for (int nt = 0; nt < 8; nt++) {
            float b0 = sCB1[nt * 8 + 2 * c], b1 = sCB1[nt * 8 + 2 * c + 1];
            acc3[nt][0] = b0; acc3[nt][1] = b1;
            acc3[nt][2] = b0; acc3[nt][3] = b1;
        }
#pragma unroll
        for (int kt = 0; kt < 4; kt++)
            gemm16(acc3, aH + kt * 32, aL + kt * 32, c1H, c1L, 2304, kt);
        __syncwarp();

        // ---- issue next tile's chunk0 (h[ndst]) — overlapped by epilogue ----
        if (tn < NTILE_E16) {
#pragma unroll
            for (int t4 = 0; t4 < 4; t4++) {
                int e2 = t4 * 4 + subrow;
                int row = __shfl_sync(0xffffffffu, ndst, e2);
                unsigned d = sbase + (e2 * 36 + ck * 4) * 4;
                cp16(d, &g_hh[row * 32 + ck * 4]);
                cp16(d + 2304, &g_hl[row * 32 + ck * 4]);
            }
            cp_commit();
        }

        // ---- coord scalar + pacc atomics ----
        float p0 = 0.f, p1 = 0.f;
#pragma unroll
        for (int nt = 0; nt < 8; nt++) {
            float w0 = sC2[nt * 8 + 2 * c], w1 = sC2[nt * 8 + 2 * c + 1];
            p0 += silu_f(acc3[nt][0]) * w0 + silu_f(acc3[nt][1]) * w1;
            p1 += silu_f(acc3[nt][2]) * w0 + silu_f(acc3[nt][3]) * w1;
        }
        p0 += __shfl_xor_sync(0xffffffffu, p0, 1); p0 += __shfl_xor_sync(0xffffffffu, p0, 2);
        p1 += __shfl_xor_sync(0xffffffffu, p1, 1); p1 += __shfl_xor_sync(0xffffffffu, p1, 2);
        int srcl = (lane & 7) * 4;
        float t0 = __shfl_sync(0xffffffffu, p0, srcl);
        float t1 = __shfl_sync(0xffffffffu, p1, srcl);
        float cc = ((el < 8) ? t0 : t1) + cb2v;

        if (lane < 16) {
            atomicAdd(&g_pacc[dst * 3 + 0], rx * cc);
            atomicAdd(&g_pacc[dst * 3 + 1], ry * cc);
            atomicAdd(&g_pacc[dst * 3 + 2], rz * cc);
        }

        src = nsrc; dst = ndst;
    }
}

// =====================================================================
// Node kernel (unchanged from R10: M=32, 512 threads)
// =====================================================================
#define NODE_SMEM_B (53760 + 16 * 9216)   // 201216

__device__ __forceinline__ void gemm_kt_lm32(float (*acc)[4],
        unsigned aH, unsigned aL, unsigned wH, unsigned wL,
        int wgb, int ktA, int ktW) {
    unsigned ah0[4], ah1[4], al0[4], al1[4];
    ldm4(ah0, aH + ktA * 32);
    ldm4(ah1, aH + 2304 + ktA * 32);
    ldm4(al0, aL + ktA * 32);
    ldm4(al1, aL + 2304 + ktA * 32);
#pragma unroll
    for (int grp = 0; grp < 4; grp++) {
        unsigned bh[4], bl[4];
        ldm4(bh, wH + grp * wgb + ktW * 32);
        ldm4(bl, wL + grp * wgb + ktW * 32);
        mma16816(acc[2 * grp],     ah0, bh);     mma16816(acc[2 * grp],     ah0, bl);     mma16816(acc[2 * grp],     al0, bh);
        mma16816(acc[2 * grp + 1], ah0, bh + 2); mma16816(acc[2 * grp + 1], ah0, bl + 2); mma16816(acc[2 * grp + 1], al0, bh + 2);
        mma16816(acc[8 + 2 * grp],     ah1, bh);     mma16816(acc[8 + 2 * grp],     ah1, bl);     mma16816(acc[8 + 2 * grp],     al1, bh);
        mma16816(acc[8 + 2 * grp + 1], ah1, bh + 2); mma16816(acc[8 + 2 * grp + 1], ah1, bl + 2); mma16816(acc[8 + 2 * grp + 1], al1, bh + 2);
    }
}

__device__ __forceinline__ void act_store32(float (*acc)[4], unsigned* oh, unsigned* ol,
                                            int g, int c, bool dosilu) {
#pragma unroll
    for (int mt = 0; mt < 2; mt++)
#pragma unroll
        for (int nt = 0; nt < 8; nt++) {
            float v0 = acc[mt * 8 + nt][0], v1 = acc[mt * 8 + nt][1];
            float v2 = acc[mt * 8 + nt][2], v3 = acc[mt * 8 + nt][3];
            if (dosilu) { v0 = silu_f(v0); v1 = silu_f(v1); v2 = silu_f(v2); v3 = silu_f(v3); }
            unsigned h01, l01, h23, l23;
            split2(make_float2(v0, v1), h01, l01);
            split2(make_float2(v2, v3), h23, l23);
            int w0 = (g + 16 * mt) * 36 + nt * 4 + c;
            int w1 = (g + 8 + 16 * mt) * 36 + nt * 4 + c;
            oh[w0] = h01; ol[w0] = l01;
            oh[w1] = h23; ol[w1] = l23;
        }
}

__global__ __launch_bounds__(512) void node_kernel(
    const float* __restrict__ nw1, const float* __restrict__ nb1,
    const float* __restrict__ nw2, const float* __restrict__ nb2,
    int layer) {
    extern __shared__ char smb[];
    __nv_bfloat16* w1h_e = (__nv_bfloat16*)(smb + 0);
    __nv_bfloat16* w1l_e = (__nv_bfloat16*)(smb + 17408);
    __nv_bfloat16* w2h_e = (__nv_bfloat16*)(smb + 34816);
    __nv_bfloat16* w2l_e = (__nv_bfloat16*)(smb + 44032);
    float* sB1 = (float*)(smb + 53248);
    float* sB2 = sB1 + 64;

    int tid = threadIdx.x;
    const float* w1g = nw1 + layer * 128 * 64;
    for (int i = tid; i < 64 * 136; i += blockDim.x) {
        int n = i / 136, k = i % 136;
        float v = (k < 128) ? w1g[k * 64 + n] : 0.0f;
        split_store(v, w1h_e + n * 136 + k, w1l_e + n * 136 + k);
    }
    const float* w2g = nw2 + layer * 64 * 64;
    for (int i = tid; i < 64 * 72; i += blockDim.x) {
        int n = i / 72, k = i % 72;
        float v = (k < 64) ? w2g[k * 64 + n] : 0.0f;
        split_store(v, w2h_e + n * 72 + k, w2l_e + n * 72 + k);
    }
    for (int i = tid; i < 64; i += blockDim.x) {
        sB1[i] = nb1[layer * 64 + i];
        sB2[i] = nb2[layer * 64 + i];
    }
    __syncthreads();

    int lane = tid & 31;
    int wl = tid >> 5;
    int g = lane >> 2;
    int c = lane & 3;
    unsigned* bhw = (unsigned*)(smb + 53760 + wl * 9216);
    unsigned* blw = bhw + 1152;

    unsigned sbase = smem_u32(bhw);
    unsigned aH = sbase + ((lane & 15) * 36) * 4 + (lane >> 4) * 16;
    unsigned aL = aH + 4608;
    int wr = lane & 7, whalf = (lane >> 3) & 1, wq = lane >> 4;
    unsigned w1H = smem_u32(w1h_e) + ((wq * 8 + wr) * 68) * 4 + whalf * 16;
    unsigned w1L = smem_u32(w1l_e) + ((wq * 8 + wr) * 68) * 4 + whalf * 16;
    unsigned w2H = smem_u32(w2h_e) + ((wq * 8 + wr) * 36) * 4 + whalf * 16;
    unsigned w2L = smem_u32(w2l_e) + ((wq * 8 + wr) * 36) * 4 + whalf * 16;

    int subrow = lane >> 3;
    int ck = lane & 7;

    int warp = (blockIdx.x * blockDim.x + tid) >> 5;
    int nwarp = (gridDim.x * blockDim.x) >> 5;

    for (int tile = warp; tile < NTILE_N; tile += nwarp) {
        int base = tile * 32;
        int n = base + lane;

#pragma unroll
        for (int t4 = 0; t4 < 8; t4++) {
            int e2 = t4 * 4 + subrow;
            int row = base + e2; if (row >= NN) row = NN - 1;
            unsigned d = sbase + (e2 * 36 + ck * 4) * 4;
            cp16(d, &g_hh[row * 32 + ck * 4]);
            cp16(d + 4608, &g_hl[row * 32 + ck * 4]);
        }
        cp_commit();

        if (n < NN) {
            float d = g_deg[n];
            if (d < 1.0f) d = 1.0f;
            float inv = 1.0f / d;
            g_pos[n * 3 + 0] += g_pacc[n * 3 + 0] * inv;
            g_pos[n * 3 + 1] += g_pacc[n * 3 + 1] * inv;
            g_pos[n * 3 + 2] += g_pacc[n * 3 + 2] * inv;
        }

        float acc[16][4];
#pragma unroll
        for (int mt = 0; mt < 2; mt++)
#pragma unroll
            for (int nt = 0; nt < 8; nt++) {
                float b0 = sB1[nt * 8 + 2 * c], b1 = sB1[nt * 8 + 2 * c + 1];
                acc[mt * 8 + nt][0] = b0; acc[mt * 8 + nt][1] = b1;
                acc[mt * 8 + nt][2] = b0; acc[mt * 8 + nt][3] = b1;
            }

        cp_wait();
        __syncwarp();
#pragma unroll
        for (int kt = 0; kt < 4; kt++)
            gemm_kt_lm32(acc, aH, aL, w1H, w1L, 4352, kt, kt);
        __syncwarp();

#pragma unroll 4
        for (int e2 = 0; e2 < 32; e2++) {
            int row = base + e2; if (row >= NN) row = NN - 1;
            float2 v = *(const float2*)&g_agg[row * 64 + 2 * lane];
            unsigned hw, lw2;
            split2(v, hw, lw2);
            bhw[e2 * 36 + lane] = hw;
            blw[e2 * 36 + lane] = lw2;
        }
        __syncwarp();
#pragma unroll
        for (int kt = 0; kt < 4; kt++)
            gemm_kt_lm32(acc, aH, aL, w1H, w1L, 4352, kt, 4 + kt);
        __syncwarp();

        act_store32(acc, bhw, blw, g, c, true);
        __syncwarp();

        float acc2[16][4];
#pragma unroll
        for (int mt = 0; mt < 2; mt++)
#pragma unroll
            for (int nt = 0; nt < 8; nt++) {
                float b0 = sB2[nt * 8 + 2 * c], b1 = sB2[nt * 8 + 2 * c + 1];
                acc2[mt * 8 + nt][0] = b0; acc2[mt * 8 + nt][1] = b1;
                acc2[mt * 8 + nt][2] = b0; acc2[mt * 8 + nt][3] = b1;
            }
#pragma unroll
        for (int kt = 0; kt < 4; kt++)
            gemm_kt_lm32(acc2, aH, aL, w2H, w2L, 2304, kt, kt);

#pragma unroll
        for (int mt = 0; mt < 2; mt++)
#pragma unroll
            for (int nt = 0; nt < 8; nt++) {
                int r0 = base + g + 16 * mt;
                int r1 = r0 + 8;
                int col = nt * 8 + 2 * c;
                if (r0 < NN) {
                    float2* p = (float2*)&g_h[r0 * 64 + col];
                    float2 o = *p;
                    o.x += acc2[mt * 8 + nt][0]; o.y += acc2[mt * 8 + nt][1];
                    *p = o;
                    unsigned hw, lw2;
                    split2(o, hw, lw2);
                    g_hh[r0 * 32 + nt * 4 + c] = hw;
                    g_hl[r0 * 32 + nt * 4 + c] = lw2;
                }
                if (r1 < NN) {
                    float2* p = (float2*)&g_h[r1 * 64 + col];
                    float2 o = *p;
                    o.x += acc2[mt * 8 + nt][2]; o.y += acc2[mt * 8 + nt][3];
                    *p = o;
                    unsigned hw, lw2;
                    split2(o, hw, lw2);
                    g_hh[r1 * 32 + nt * 4 + c] = hw;
                    g_hl[r1 * 32 + nt * 4 + c] = lw2;
                }
            }
        __syncwarp();
    }
}

// ---------------- pooling ----------------
__global__ void pool_zero_kernel() {
    int i = blockIdx.x * blockDim.x + threadIdx.x;
    int st = gridDim.x * blockDim.x;
    for (int j = i; j < NG * HD; j += st) g_gsum[j] = 0.0f;
    for (int j = i; j < NG; j += st) g_gcnt[j] = 0.0f;
}

__global__ void pool_kernel(const int* __restrict__ batch) {
    int tid = threadIdx.x;
    int lane = tid & 31;
    int warp = (blockIdx.x * blockDim.x + tid) >> 5;
    int nwarp = (gridDim.x * blockDim.x) >> 5;
    for (int n = warp; n < NN; n += nwarp) {
        int b = batch[n];
        atomicAdd(&g_gsum[b * HD + lane], g_h[n * HD + lane]);
        atomicAdd(&g_gsum[b * HD + 32 + lane], g_h[n * HD + 32 + lane]);
        if (lane == 0) atomicAdd(&g_gcnt[b], 1.0f);
    }
}

// ---------------- per-graph: pre-MLP, 4-qubit circuit, post-MLP ----------------
__global__ void final_kernel(const float* __restrict__ prew, const float* __restrict__ preb,
                             const float* __restrict__ qw,
                             const float* __restrict__ pw1, const float* __restrict__ pb1,
                             const float* __restrict__ pw2, const float* __restrict__ pb2,
                             float* __restrict__ out) {
    int g = threadIdx.x;
    if (g >= NG) return;
    float cnt = g_gcnt[g];
    if (cnt < 1.0f) cnt = 1.0f;
    float qin[4];
    for (int q = 0; q < 4; q++) qin[q] = preb[q];
    for (int k = 0; k < HD; k++) {
        float gv = g_gsum[g * HD + k] / cnt;
        for (int q = 0; q < 4; q++) qin[q] += gv * prew[k * 4 + q];
    }

    float pr[16], pi[16];
    for (int i = 0; i < 16; i++) { pr[i] = 0.0f; pi[i] = 0.0f; }
    pr[0] = 1.0f;

    for (int q = 0; q < 4; q++) {
        int s = 8 >> q;
        float ch = cosf(qin[q] * 0.5f);
        float sh = sinf(qin[q] * 0.5f);
        for (int i = 0; i < 16; i++) {
            if (i & s) continue;
            int j = i | s;
            float ar = pr[i], ai = pi[i], br = pr[j], bi = pi[j];
            pr[i] = ch * ar + sh * bi;  pi[i] = ch * ai - sh * br;
            pr[j] = ch * br + sh * ai;  pi[j] = ch * bi - sh * ar;
        }
    }
    for (int l = 0; l < 2; l++) {
        for (int q = 0; q < 4; q++) {
            int s = 8 >> q;
            float ch = cosf(qw[l * 4 + q] * 0.5f);
            float sh = sinf(qw[l * 4 + q] * 0.5f);
            for (int i = 0; i < 16; i++) {
                if (i & s) continue;
                int j = i | s;
                float ar = pr[i], ai = pi[i], br = pr[j], bi = pi[j];
                pr[i] = ch * ar - sh * br;  pi[i] = ch * ai - sh * bi;
                pr[j] = sh * ar + ch * br;  pi[j] = sh * ai + ch * bi;
            }
        }
        for (int q = 0; q < 4; q++) {
            int cs = 8 >> q;
            int ts = 8 >> ((q + 1) & 3);
            for (int i = 0; i < 16; i++) {
                if ((i & cs) && !(i & ts)) {
                    int j = i | ts;
                    float t;
                    t = pr[i]; pr[i] = pr[j]; pr[j] = t;
                    t = pi[i]; pi[i] = pi[j]; pi[j] = t;
                }
            }
        }
    }
    float qo[4] = {0.0f, 0.0f, 0.0f, 0.0f};
    for (int i = 0; i < 16; i++) {
        float p = pr[i] * pr[i] + pi[i] * pi[i];
        for (int q = 0; q < 4; q++) qo[q] += (i & (8 >> q)) ? -p : p;
    }

    float acc = pb2[0];
    for (int j = 0; j < HD; j++) {
        float t = pb1[j];
        for (int q = 0; q < 4; q++) t += qo[q] * pw1[q * HD + j];
        acc += silu_f(t) * pw2[j];
    }
    out[g] = acc;
}

// ---------------- launch ----------------
extern "C" void kernel_launch(void* const* d_in, const int* in_sizes, int n_in,
                              void* d_out, int out_size) {
    const int* nt = (const int*)d_in[0];
    const float* pos = (const float*)d_in[1];
    const int* ei = (const int*)d_in[2];
    const float* ea = (const float*)d_in[3];
    const int* batch = (const int*)d_in[4];
    const float* emb = (const float*)d_in[5];
    const float* ew1 = (const float*)d_in[6];
    const float* eb1 = (const float*)d_in[7];
    const float* ew2 = (const float*)d_in[8];
    const float* eb2 = (const float*)d_in[9];
    const float* cw1 = (const float*)d_in[10];
    const float* cb1 = (const float*)d_in[11];
    const float* cw2 = (const float*)d_in[12];
    const float* cb2 = (const float*)d_in[13];
    const float* nw1 = (const float*)d_in[14];
    const float* nb1 = (const float*)d_in[15];
    const float* nw2 = (const float*)d_in[16];
    const float* nb2 = (const float*)d_in[17];
    const float* prew = (const float*)d_in[18];
    const float* preb = (const float*)d_in[19];
    const float* qw = (const float*)d_in[20];
    const float* pw1 = (const float*)d_in[21];
    const float* pb1 = (const float*)d_in[22];
    const float* pw2 = (const float*)d_in[23];
    const float* pb2 = (const float*)d_in[24];
    float* out = (float*)d_out;

    cudaFuncSetAttribute(edge_kernel, cudaFuncAttributeMaxDynamicSharedMemorySize, EDGE_SMEM_B);
    cudaFuncSetAttribute(node_kernel, cudaFuncAttributeMaxDynamicSharedMemorySize, NODE_SMEM_B);

    init_kernel<<<512, 256>>>(nt, emb, pos);
    deg_kernel<<<512, 256>>>(ei);
    for (int l = 0; l < NL; l++) {
        zero_layer_kernel<<<512, 256>>>();
        edge_kernel<<<148, 768, EDGE_SMEM_B>>>(ei, ea, ew1, eb1, ew2, eb2,
                                               cw1, cb1, cw2, cb2, l);
        node_kernel<<<148, 512, NODE_SMEM_B>>>(nw1, nb1, nw2, nb2, l);
    }
    pool_zero_kernel<<<64, 256>>>();
    pool_kernel<<<512, 256>>>(batch);
    final_kernel<<<1, 128>>>(prew, preb, qw, pw1, pb1, pw2, pb2, out);
}